// round 1
// baseline (speedup 1.0000x reference)
#include <cuda_runtime.h>
#include <stdint.h>

#define NB    16
#define CCH   7
#define FCH   128
#define CW    64
#define FW    256
#define NPTS  1024
#define NIMP  768
#define NCOV  256
#define NOVER 7168
#define SORTN 8192
#define HID   256
#define FEATC 135

// scratch (no cudaMalloc allowed)
__device__ float g_top2[NB * 2 * CW * CW];
__device__ float g_unc[NB * NOVER];

struct BL {
    int   i00, i01, i10, i11;
    float m00, m01, m10, m11;
    float wx, wy;
};

// Replicates the reference's point_sample coordinate math with explicit
// rounding (no FMA contraction) so the top-k selection is bit-stable.
__device__ __forceinline__ void bl_setup(float px, float py, int W, BL& o) {
    float gx = __fsub_rn(__fmul_rn(2.0f, px), 1.0f);
    float gy = __fsub_rn(__fmul_rn(2.0f, py), 1.0f);
    float x  = __fmul_rn(__fsub_rn(__fmul_rn(__fadd_rn(gx, 1.0f), (float)W), 1.0f), 0.5f);
    float y  = __fmul_rn(__fsub_rn(__fmul_rn(__fadd_rn(gy, 1.0f), (float)W), 1.0f), 0.5f);
    float x0f = floorf(x), y0f = floorf(y);
    o.wx = __fsub_rn(x, x0f);
    o.wy = __fsub_rn(y, y0f);
    float x1f = __fadd_rn(x0f, 1.0f), y1f = __fadd_rn(y0f, 1.0f);
    float wm1 = (float)(W - 1);
    bool vx0 = (x0f >= 0.0f) && (x0f <= wm1);
    bool vx1 = (x1f >= 0.0f) && (x1f <= wm1);
    bool vy0 = (y0f >= 0.0f) && (y0f <= wm1);
    bool vy1 = (y1f >= 0.0f) && (y1f <= wm1);
    int ix0 = min(max((int)x0f, 0), W - 1);
    int ix1 = min(max((int)x1f, 0), W - 1);
    int iy0 = min(max((int)y0f, 0), W - 1);
    int iy1 = min(max((int)y1f, 0), W - 1);
    o.i00 = iy0 * W + ix0; o.i01 = iy0 * W + ix1;
    o.i10 = iy1 * W + ix0; o.i11 = iy1 * W + ix1;
    o.m00 = (vx0 && vy0) ? 1.0f : 0.0f;
    o.m01 = (vx1 && vy0) ? 1.0f : 0.0f;
    o.m10 = (vx0 && vy1) ? 1.0f : 0.0f;
    o.m11 = (vx1 && vy1) ? 1.0f : 0.0f;
}

__device__ __forceinline__ float bl_sample(const float* __restrict__ plane, const BL& o) {
    float v00 = __fmul_rn(plane[o.i00], o.m00);
    float v01 = __fmul_rn(plane[o.i01], o.m01);
    float v10 = __fmul_rn(plane[o.i10], o.m10);
    float v11 = __fmul_rn(plane[o.i11], o.m11);
    float owx = __fsub_rn(1.0f, o.wx), owy = __fsub_rn(1.0f, o.wy);
    float t0 = __fmul_rn(__fmul_rn(v00, owx),  owy);
    float t1 = __fmul_rn(__fmul_rn(v01, o.wx), owy);
    float t2 = __fmul_rn(__fmul_rn(v10, owx),  o.wy);
    float t3 = __fmul_rn(__fmul_rn(v11, o.wx), o.wy);
    return __fadd_rn(__fadd_rn(__fadd_rn(t0, t1), t2), t3);
}

// K1: per-pixel top-2 of the 7 coarse channels.
__global__ void k_top2(const float* __restrict__ coarse) {
    int i = blockIdx.x * blockDim.x + threadIdx.x;
    if (i >= NB * CW * CW) return;
    int b = i >> 12;
    int pix = i & 4095;
    const float* p = coarse + (size_t)b * CCH * 4096 + pix;
    float m1 = __int_as_float(0xff800000), m2 = m1;  // -inf
#pragma unroll
    for (int c = 0; c < CCH; c++) {
        float v = p[c * 4096];
        if (v > m1) { m2 = m1; m1 = v; }
        else if (v > m2) { m2 = v; }
    }
    g_top2[(size_t)b * 2 * 4096 + pix]        = m1;
    g_top2[(size_t)b * 2 * 4096 + 4096 + pix] = m2;
}

// K2: uncertainty at all over_gen points.
__global__ void k_unc(const float* __restrict__ over_gen) {
    int i = blockIdx.x * blockDim.x + threadIdx.x;
    if (i >= NB * NOVER) return;
    int b = i / NOVER;
    float2 pt = ((const float2*)over_gen)[i];
    BL o;
    bl_setup(pt.x, pt.y, CW, o);
    const float* p0 = g_top2 + (size_t)b * 2 * 4096;
    float s0 = bl_sample(p0, o);
    float s1 = bl_sample(p0 + 4096, o);
    g_unc[i] = -__fsub_rn(s0, s1);
}

// K3: stable top-768 (value desc, index asc) via 64-bit-key bitonic sort,
// then emit points = [over_gen[idx], coverage] into d_out.
__global__ void __launch_bounds__(1024) k_topk(const float* __restrict__ over_gen,
                                               const float* __restrict__ coverage,
                                               float* __restrict__ pts_out) {
    extern __shared__ unsigned long long s_keys[];
    int b = blockIdx.x;
    int t = threadIdx.x;

    for (int i = t; i < SORTN; i += 1024) {
        unsigned long long key;
        if (i < NOVER) {
            unsigned u = __float_as_uint(g_unc[b * NOVER + i]);
            u = (u & 0x80000000u) ? ~u : (u ^ 0x80000000u);  // order-preserving map
            key = ((unsigned long long)(~u) << 13) | (unsigned)i;  // desc value, asc idx
        } else {
            key = ~0ull;
        }
        s_keys[i] = key;
    }
    __syncthreads();

    for (unsigned k = 2; k <= SORTN; k <<= 1) {
        for (unsigned j = k >> 1; j > 0; j >>= 1) {
            for (unsigned i = t; i < SORTN; i += 1024) {
                unsigned ixj = i ^ j;
                if (ixj > i) {
                    unsigned long long a = s_keys[i], c = s_keys[ixj];
                    bool up = ((i & k) == 0);
                    if ((a > c) == up) { s_keys[i] = c; s_keys[ixj] = a; }
                }
            }
            __syncthreads();
        }
    }

    float* dst = pts_out + (size_t)b * NPTS * 2;
    const float2* og = (const float2*)over_gen + (size_t)b * NOVER;
    for (int i = t; i < NIMP; i += 1024) {
        int n = (int)(s_keys[i] & 0x1FFFull);
        float2 p = og[n];
        dst[i * 2 + 0] = p.x;
        dst[i * 2 + 1] = p.y;
    }
    const float2* cv = (const float2*)coverage + (size_t)b * NCOV;
    for (int i = t; i < NCOV; i += 1024) {
        float2 p = cv[i];
        dst[(NIMP + i) * 2 + 0] = p.x;
        dst[(NIMP + i) * 2 + 1] = p.y;
    }
}

// K4: per (batch, 64-point tile): gather 135-ch features into smem,
// smem-tiled GEMM [64,135]x[135,256] + relu, then [64,256]x[256,7] -> rend.
// smem floats: feat 8704 | w1c 6912 | h 16384 | w2 1792 | masks 512 | w 256 | idx 512
#define SM_FEAT 0
#define SM_W1C  8704
#define SM_H    15616
#define SM_W2   32000
#define SM_CM   33792
#define SM_CWT  34304
#define SM_CI   34560
#define SM_TOT  35072  // floats -> 140288 bytes

__global__ void __launch_bounds__(256, 1) k_mlp(
    const float* __restrict__ coarse, const float* __restrict__ fine,
    const float* __restrict__ w1, const float* __restrict__ b1,
    const float* __restrict__ w2, const float* __restrict__ b2,
    const float* __restrict__ pts, float* __restrict__ rend)
{
    extern __shared__ float sm[];
    float* feat = sm + SM_FEAT;
    float* w1c  = sm + SM_W1C;
    float* hbuf = sm + SM_H;
    float* w2s  = sm + SM_W2;
    float* cm   = sm + SM_CM;   // [8][64] masks: c00..c11, f00..f11
    float* cwt  = sm + SM_CWT;  // [4][64]: cwx,cwy,fwx,fwy
    int*   ci   = (int*)(sm + SM_CI);  // [8][64] offsets

    int t  = threadIdx.x;
    int b  = blockIdx.x >> 4;
    int p0 = (blockIdx.x & 15) * 64;

    // coords for 64 points (both resolutions)
    if (t < 64) {
        float2 p = ((const float2*)pts)[(size_t)b * NPTS + p0 + t];
        BL oc, of;
        bl_setup(p.x, p.y, CW, oc);
        bl_setup(p.x, p.y, FW, of);
        cm[0 * 64 + t] = oc.m00; cm[1 * 64 + t] = oc.m01;
        cm[2 * 64 + t] = oc.m10; cm[3 * 64 + t] = oc.m11;
        cm[4 * 64 + t] = of.m00; cm[5 * 64 + t] = of.m01;
        cm[6 * 64 + t] = of.m10; cm[7 * 64 + t] = of.m11;
        cwt[0 * 64 + t] = oc.wx; cwt[1 * 64 + t] = oc.wy;
        cwt[2 * 64 + t] = of.wx; cwt[3 * 64 + t] = of.wy;
        ci[0 * 64 + t] = oc.i00; ci[1 * 64 + t] = oc.i01;
        ci[2 * 64 + t] = oc.i10; ci[3 * 64 + t] = oc.i11;
        ci[4 * 64 + t] = of.i00; ci[5 * 64 + t] = of.i01;
        ci[6 * 64 + t] = of.i10; ci[7 * 64 + t] = of.i11;
    }
    // init h with bias, stage w2
    for (int i = t; i < 64 * HID; i += 256) hbuf[i] = b1[i & 255];
    for (int i = t; i < HID * 7; i += 256) w2s[i] = w2[i];
    __syncthreads();

    // gather coarse features: 64p x 7c
    for (int it = 0; it < 2; it++) {
        int task = it * 256 + t;
        if (task < 64 * CCH) {
            int p = task / CCH, c = task % CCH;
            const float* plane = coarse + ((size_t)b * CCH + c) * 4096;
            float wx = cwt[0 * 64 + p], wy = cwt[1 * 64 + p];
            float v00 = __fmul_rn(plane[ci[0 * 64 + p]], cm[0 * 64 + p]);
            float v01 = __fmul_rn(plane[ci[1 * 64 + p]], cm[1 * 64 + p]);
            float v10 = __fmul_rn(plane[ci[2 * 64 + p]], cm[2 * 64 + p]);
            float v11 = __fmul_rn(plane[ci[3 * 64 + p]], cm[3 * 64 + p]);
            float owx = 1.0f - wx, owy = 1.0f - wy;
            feat[p * 136 + c] = v00 * owx * owy + v01 * wx * owy + v10 * owx * wy + v11 * wx * wy;
        }
    }
    // gather fine features: 64p x 128c
    for (int it = 0; it < 32; it++) {
        int task = it * 256 + t;
        int c = task & 127, p = task >> 7;
        const float* plane = fine + ((size_t)b * FCH + c) * 65536;
        float wx = cwt[2 * 64 + p], wy = cwt[3 * 64 + p];
        float v00 = __fmul_rn(plane[ci[4 * 64 + p]], cm[4 * 64 + p]);
        float v01 = __fmul_rn(plane[ci[5 * 64 + p]], cm[5 * 64 + p]);
        float v10 = __fmul_rn(plane[ci[6 * 64 + p]], cm[6 * 64 + p]);
        float v11 = __fmul_rn(plane[ci[7 * 64 + p]], cm[7 * 64 + p]);
        float owx = 1.0f - wx, owy = 1.0f - wy;
        feat[p * 136 + 7 + c] = v00 * owx * owy + v01 * wx * owy + v10 * owx * wy + v11 * wx * wy;
    }
    __syncthreads();

    // GEMM1: h[64][256] += feat[64][135] * w1[135][256], k-chunks of 27 in smem
    int d4   = (t & 63) * 4;
    int prow = t >> 6;  // 0..3
    for (int cc0 = 0; cc0 < FEATC; cc0 += 27) {
        for (int i = t; i < 27 * HID; i += 256)
            w1c[i] = w1[(cc0 + (i >> 8)) * HID + (i & 255)];
        __syncthreads();
        for (int pb = 0; pb < 16; pb++) {
            int p = pb * 4 + prow;
            float4 acc = *(float4*)&hbuf[p * HID + d4];
            const float* fr = &feat[p * 136 + cc0];
#pragma unroll
            for (int c = 0; c < 27; c++) {
                float f = fr[c];
                float4 w = *(float4*)&w1c[c * HID + d4];
                acc.x += f * w.x; acc.y += f * w.y; acc.z += f * w.z; acc.w += f * w.w;
            }
            *(float4*)&hbuf[p * HID + d4] = acc;
        }
        __syncthreads();
    }

    // GEMM2: rend[64][7] = relu(h) * w2 + b2
    for (int task = t; task < 64 * 7; task += 256) {
        int p = task / 7, k = task % 7;
        float acc = b2[k];
        for (int d = 0; d < HID; d++) {
            float hv = fmaxf(hbuf[p * HID + d], 0.0f);
            acc += hv * w2s[d * 7 + k];
        }
        rend[((size_t)b * 7 + k) * NPTS + p0 + p] = acc;
    }
}

extern "C" void kernel_launch(void* const* d_in, const int* in_sizes, int n_in,
                              void* d_out, int out_size) {
    (void)in_sizes; (void)n_in; (void)out_size;
    const float* fine     = (const float*)d_in[0];
    const float* coarse   = (const float*)d_in[1];
    const float* w1       = (const float*)d_in[2];
    const float* b1       = (const float*)d_in[3];
    const float* w2       = (const float*)d_in[4];
    const float* b2       = (const float*)d_in[5];
    const float* over_gen = (const float*)d_in[6];
    const float* coverage = (const float*)d_in[7];

    float* rend = (float*)d_out;                 // [16][7][1024]
    float* pts  = rend + NB * CCH * NPTS;        // [16][1024][2]

    cudaFuncSetAttribute(k_topk, cudaFuncAttributeMaxDynamicSharedMemorySize, SORTN * 8);
    cudaFuncSetAttribute(k_mlp,  cudaFuncAttributeMaxDynamicSharedMemorySize, SM_TOT * 4);

    k_top2<<<(NB * CW * CW) / 256, 256>>>(coarse);
    k_unc<<<(NB * NOVER) / 256, 256>>>(over_gen);
    k_topk<<<NB, 1024, SORTN * 8>>>(over_gen, coverage, pts);
    k_mlp<<<NB * 16, 256, SM_TOT * 4>>>(coarse, fine, w1, b1, w2, b2, pts, rend);
}

// round 2
// speedup vs baseline: 1.1633x; 1.1633x over previous
#include <cuda_runtime.h>
#include <stdint.h>

#define NB    16
#define CCH   7
#define FCH   128
#define CW    64
#define FW    256
#define NPTS  1024
#define NIMP  768
#define NCOV  256
#define NOVER 7168
#define HID   256
#define FEATC 135
#define FSTR  136   // feat row stride: fine[0..127], coarse[128..134], pad

// scratch (no cudaMalloc allowed)
__device__ float g_top2[NB * 2 * CW * CW];
__device__ float g_unc[NB * NOVER];
__device__ float g_feat[NB * NPTS * FSTR];

struct BL {
    int   i00, i01, i10, i11;
    float m00, m01, m10, m11;
    float wx, wy;
};

// Replicates the reference's point_sample coordinate math with explicit
// rounding (no FMA contraction) so the top-k selection is bit-stable.
__device__ __forceinline__ void bl_setup(float px, float py, int W, BL& o) {
    float gx = __fsub_rn(__fmul_rn(2.0f, px), 1.0f);
    float gy = __fsub_rn(__fmul_rn(2.0f, py), 1.0f);
    float x  = __fmul_rn(__fsub_rn(__fmul_rn(__fadd_rn(gx, 1.0f), (float)W), 1.0f), 0.5f);
    float y  = __fmul_rn(__fsub_rn(__fmul_rn(__fadd_rn(gy, 1.0f), (float)W), 1.0f), 0.5f);
    float x0f = floorf(x), y0f = floorf(y);
    o.wx = __fsub_rn(x, x0f);
    o.wy = __fsub_rn(y, y0f);
    float x1f = __fadd_rn(x0f, 1.0f), y1f = __fadd_rn(y0f, 1.0f);
    float wm1 = (float)(W - 1);
    bool vx0 = (x0f >= 0.0f) && (x0f <= wm1);
    bool vx1 = (x1f >= 0.0f) && (x1f <= wm1);
    bool vy0 = (y0f >= 0.0f) && (y0f <= wm1);
    bool vy1 = (y1f >= 0.0f) && (y1f <= wm1);
    int ix0 = min(max((int)x0f, 0), W - 1);
    int ix1 = min(max((int)x1f, 0), W - 1);
    int iy0 = min(max((int)y0f, 0), W - 1);
    int iy1 = min(max((int)y1f, 0), W - 1);
    o.i00 = iy0 * W + ix0; o.i01 = iy0 * W + ix1;
    o.i10 = iy1 * W + ix0; o.i11 = iy1 * W + ix1;
    o.m00 = (vx0 && vy0) ? 1.0f : 0.0f;
    o.m01 = (vx1 && vy0) ? 1.0f : 0.0f;
    o.m10 = (vx0 && vy1) ? 1.0f : 0.0f;
    o.m11 = (vx1 && vy1) ? 1.0f : 0.0f;
}

__device__ __forceinline__ float bl_sample(const float* __restrict__ plane, const BL& o) {
    float v00 = __fmul_rn(plane[o.i00], o.m00);
    float v01 = __fmul_rn(plane[o.i01], o.m01);
    float v10 = __fmul_rn(plane[o.i10], o.m10);
    float v11 = __fmul_rn(plane[o.i11], o.m11);
    float owx = __fsub_rn(1.0f, o.wx), owy = __fsub_rn(1.0f, o.wy);
    float t0 = __fmul_rn(__fmul_rn(v00, owx),  owy);
    float t1 = __fmul_rn(__fmul_rn(v01, o.wx), owy);
    float t2 = __fmul_rn(__fmul_rn(v10, owx),  o.wy);
    float t3 = __fmul_rn(__fmul_rn(v11, o.wx), o.wy);
    return __fadd_rn(__fadd_rn(__fadd_rn(t0, t1), t2), t3);
}

// K1: per-pixel top-2 of the 7 coarse channels.
__global__ void k_top2(const float* __restrict__ coarse) {
    int i = blockIdx.x * blockDim.x + threadIdx.x;
    if (i >= NB * CW * CW) return;
    int b = i >> 12;
    int pix = i & 4095;
    const float* p = coarse + (size_t)b * CCH * 4096 + pix;
    float m1 = __int_as_float(0xff800000), m2 = m1;
#pragma unroll
    for (int c = 0; c < CCH; c++) {
        float v = p[c * 4096];
        if (v > m1) { m2 = m1; m1 = v; }
        else if (v > m2) { m2 = v; }
    }
    g_top2[(size_t)b * 2 * 4096 + pix]        = m1;
    g_top2[(size_t)b * 2 * 4096 + 4096 + pix] = m2;
}

// K2: uncertainty at all over_gen points.
__global__ void k_unc(const float* __restrict__ over_gen) {
    int i = blockIdx.x * blockDim.x + threadIdx.x;
    if (i >= NB * NOVER) return;
    int b = i / NOVER;
    float2 pt = ((const float2*)over_gen)[i];
    BL o;
    bl_setup(pt.x, pt.y, CW, o);
    const float* p0 = g_top2 + (size_t)b * 2 * 4096;
    float s0 = bl_sample(p0, o);
    float s1 = bl_sample(p0 + 4096, o);
    g_unc[i] = -__fsub_rn(s0, s1);
}

// K3: exact stable top-768 via radix-select on 48-bit composite key
// (value desc via order-mapped ~bits, idx asc). Keys are unique (idx part),
// so the 768th-smallest key is exact and needs no tie handling.
// smem: keys[7168] ull | buf[1024] ull | hist[256] u32 | ctrl
#define SEL_KEYS 0
#define SEL_BUF  (NOVER)
#define SEL_SMEM ((NOVER + 1024) * 8 + 256 * 4 + 32)

__global__ void __launch_bounds__(1024) k_select(const float* __restrict__ over_gen,
                                                 const float* __restrict__ coverage,
                                                 float* __restrict__ pts_out) {
    extern __shared__ unsigned long long s_keys[];
    unsigned long long* buf = s_keys + SEL_BUF;
    unsigned* hist = (unsigned*)(s_keys + SEL_BUF + 1024);
    unsigned long long* s_prefix = (unsigned long long*)(hist + 256);
    int* s_rank = (int*)(s_prefix + 1);
    int* s_cnt  = s_rank + 1;

    int b = blockIdx.x;
    int t = threadIdx.x;

    for (int i = t; i < NOVER; i += 1024) {
        unsigned u = __float_as_uint(g_unc[b * NOVER + i]);
        u = (u & 0x80000000u) ? ~u : (u ^ 0x80000000u);  // order-preserving
        s_keys[i] = ((unsigned long long)(~u) << 13) | (unsigned)i;
    }
    if (t == 0) { *s_prefix = 0ull; *s_rank = NIMP; *s_cnt = 0; }
    __syncthreads();

    // 6 byte-passes, MSB->LSB over bits [47:0]
    for (int byte = 5; byte >= 0; byte--) {
        int shift = byte * 8;
        if (t < 256) hist[t] = 0;
        __syncthreads();
        unsigned long long pref = *s_prefix;
        for (int i = t; i < NOVER; i += 1024) {
            unsigned long long k = s_keys[i];
            if ((k >> (shift + 8)) == pref)
                atomicAdd(&hist[(unsigned)(k >> shift) & 255u], 1u);
        }
        __syncthreads();
        if (t == 0) {
            int rank = *s_rank;
            unsigned cum = 0;
            int sel = 255;
            for (int d = 0; d < 256; d++) {
                unsigned h = hist[d];
                if (cum + h >= (unsigned)rank) { sel = d; break; }
                cum += h;
            }
            *s_rank = rank - (int)cum;
            *s_prefix = (pref << 8) | (unsigned)sel;
        }
        __syncthreads();
    }

    // compact the exact 768 winners (keys <= K*)
    unsigned long long kstar = *s_prefix;
    for (int i = t; i < NOVER; i += 1024) {
        unsigned long long k = s_keys[i];
        if (k <= kstar) {
            int pos = atomicAdd(s_cnt, 1);
            buf[pos] = k;
        }
    }
    // pad to 1024
    if (t >= NIMP) buf[t] = ~0ull;
    __syncthreads();

    // bitonic sort 1024 keys, one element per thread
    for (unsigned k = 2; k <= 1024; k <<= 1) {
        for (unsigned j = k >> 1; j > 0; j >>= 1) {
            unsigned i = t, ixj = i ^ j;
            if (ixj > i) {
                unsigned long long a = buf[i], c = buf[ixj];
                bool up = ((i & k) == 0);
                if ((a > c) == up) { buf[i] = c; buf[ixj] = a; }
            }
            __syncthreads();
        }
    }

    float* dst = pts_out + (size_t)b * NPTS * 2;
    if (t < NIMP) {
        int n = (int)(buf[t] & 0x1FFFull);
        float2 p = ((const float2*)over_gen)[(size_t)b * NOVER + n];
        dst[t * 2 + 0] = p.x;
        dst[t * 2 + 1] = p.y;
    } else {
        int i = t - NIMP;  // 0..255
        float2 p = ((const float2*)coverage)[(size_t)b * NCOV + i];
        dst[(NIMP + i) * 2 + 0] = p.x;
        dst[(NIMP + i) * 2 + 1] = p.y;
    }
}

// K4a: coarse gather. One thread per (b,p): 7 channels into feat[128..134].
__global__ void k_gather_coarse(const float* __restrict__ coarse,
                                const float* __restrict__ pts) {
    int i = blockIdx.x * blockDim.x + threadIdx.x;
    if (i >= NB * NPTS) return;
    int b = i >> 10;
    float2 p = ((const float2*)pts)[i];
    BL o;
    bl_setup(p.x, p.y, CW, o);
    float owx = 1.0f - o.wx, owy = 1.0f - o.wy;
    float w00 = owx * owy, w01 = o.wx * owy, w10 = owx * o.wy, w11 = o.wx * o.wy;
    float* dst = g_feat + (size_t)i * FSTR + FCH;
    const float* base = coarse + (size_t)b * CCH * 4096;
#pragma unroll
    for (int c = 0; c < CCH; c++) {
        const float* pl = base + c * 4096;
        float v = pl[o.i00] * o.m00 * w00 + pl[o.i01] * o.m01 * w01
                + pl[o.i10] * o.m10 * w10 + pl[o.i11] * o.m11 * w11;
        dst[c] = v;
    }
}

// K4b: fine gather. One thread per (b,p,cg) with cg covering 8 channels.
// 262144 threads -> saturates random-gather DRAM path.
__global__ void k_gather_fine(const float* __restrict__ fine,
                              const float* __restrict__ pts) {
    int g = blockIdx.x * blockDim.x + threadIdx.x;
    int cg = g & 15;
    int bp = g >> 4;           // (b,p) in 0..16383
    int b  = bp >> 10;
    float2 p = ((const float2*)pts)[bp];
    BL o;
    bl_setup(p.x, p.y, FW, o);
    float owx = 1.0f - o.wx, owy = 1.0f - o.wy;
    float w00 = owx * owy, w01 = o.wx * owy, w10 = owx * o.wy, w11 = o.wx * o.wy;
    const float* base = fine + ((size_t)b * FCH + cg * 8) * 65536;
    float v[8];
#pragma unroll
    for (int j = 0; j < 8; j++) {
        const float* pl = base + (size_t)j * 65536;
        v[j] = pl[o.i00] * o.m00 * w00 + pl[o.i01] * o.m01 * w01
             + pl[o.i10] * o.m10 * w10 + pl[o.i11] * o.m11 * w11;
    }
    float* dst = g_feat + (size_t)bp * FSTR + cg * 8;
    *(float4*)(dst)     = make_float4(v[0], v[1], v[2], v[3]);
    *(float4*)(dst + 4) = make_float4(v[4], v[5], v[6], v[7]);
}

// K5: GEMM. 256 CTAs x 64 points. Each thread: 4 pts x 16 cols fp32 register
// tile; k-chunked w1 in smem; fused relu + [256x7] epilogue with cross-cg
// smem reduction.
// smem floats: feat 8704 | w1s 8192 (reused as part 7168) | w2s 1792
#define GM_SF   0
#define GM_W1S  8704
#define GM_W2S  16896
#define GM_TOT  18688   // floats -> 74752 bytes

__global__ void __launch_bounds__(256) k_gemm(
    const float* __restrict__ w1, const float* __restrict__ b1,
    const float* __restrict__ w2, const float* __restrict__ b2,
    float* __restrict__ rend)
{
    extern __shared__ float sm[];
    float* sf   = sm + GM_SF;
    float* w1s  = sm + GM_W1S;
    float* w2s  = sm + GM_W2S;
    float* part = sm + GM_W1S;  // reused after GEMM1

    int t  = threadIdx.x;
    int b  = blockIdx.x >> 4;
    int p0 = (blockIdx.x & 15) * 64;
    int cg = t & 15;     // col group: cols cg*16..cg*16+15
    int pg = t >> 4;     // point group: pts pg*4..pg*4+3

    // stage feat tile [64][136] and w2 [256][7]
    const float4* gsrc = (const float4*)(g_feat + (size_t)(b * NPTS + p0) * FSTR);
    for (int i = t; i < 64 * FSTR / 4; i += 256) ((float4*)sf)[i] = gsrc[i];
    for (int i = t; i < HID * 7; i += 256) w2s[i] = w2[i];

    // init accumulators with bias
    float acc[4][16];
    {
        float bv[16];
#pragma unroll
        for (int j = 0; j < 16; j++) bv[j] = b1[cg * 16 + j];
#pragma unroll
        for (int i = 0; i < 4; i++)
#pragma unroll
            for (int j = 0; j < 16; j++) acc[i][j] = bv[j];
    }
    __syncthreads();

    // GEMM1: k-chunks of 32 over 135; feat k<128 -> w1 row 7+k, else row k-128
    for (int k0 = 0; k0 < FEATC; k0 += 32) {
        int kcnt = min(32, FEATC - k0);
        __syncthreads();
        for (int i = t; i < kcnt * HID; i += 256) {
            int kk = i >> 8, c = i & 255;
            int row = k0 + kk;
            int srow = (row < FCH) ? (CCH + row) : (row - FCH);
            w1s[kk * HID + c] = w1[srow * HID + c];
        }
        __syncthreads();
        for (int kk = 0; kk < kcnt; kk++) {
            float f0 = sf[(pg * 4 + 0) * FSTR + k0 + kk];
            float f1 = sf[(pg * 4 + 1) * FSTR + k0 + kk];
            float f2 = sf[(pg * 4 + 2) * FSTR + k0 + kk];
            float f3 = sf[(pg * 4 + 3) * FSTR + k0 + kk];
#pragma unroll
            for (int q = 0; q < 4; q++) {
                float4 w = *(float4*)&w1s[kk * HID + cg * 16 + q * 4];
                acc[0][q*4+0] += f0 * w.x; acc[0][q*4+1] += f0 * w.y;
                acc[0][q*4+2] += f0 * w.z; acc[0][q*4+3] += f0 * w.w;
                acc[1][q*4+0] += f1 * w.x; acc[1][q*4+1] += f1 * w.y;
                acc[1][q*4+2] += f1 * w.z; acc[1][q*4+3] += f1 * w.w;
                acc[2][q*4+0] += f2 * w.x; acc[2][q*4+1] += f2 * w.y;
                acc[2][q*4+2] += f2 * w.z; acc[2][q*4+3] += f2 * w.w;
                acc[3][q*4+0] += f3 * w.x; acc[3][q*4+1] += f3 * w.y;
                acc[3][q*4+2] += f3 * w.z; acc[3][q*4+3] += f3 * w.w;
            }
        }
    }
    __syncthreads();  // done reading w1s; reuse as part

    // GEMM2 partials: relu(acc) * w2 over this thread's 16 d's
#pragma unroll
    for (int i = 0; i < 4; i++) {
        float pr[7];
#pragma unroll
        for (int k = 0; k < 7; k++) pr[k] = 0.0f;
#pragma unroll
        for (int j = 0; j < 16; j++) {
            float hv = fmaxf(acc[i][j], 0.0f);
            const float* wr = &w2s[(cg * 16 + j) * 7];
#pragma unroll
            for (int k = 0; k < 7; k++) pr[k] += hv * wr[k];
        }
        float* pp = &part[((pg * 4 + i) * 16 + cg) * 7];
#pragma unroll
        for (int k = 0; k < 7; k++) pp[k] = pr[k];
    }
    __syncthreads();

    // reduce across 16 col groups, add b2, write rend[b][k][p0+p]
    for (int task = t; task < 64 * 7; task += 256) {
        int p = task / 7, k = task % 7;
        float s = b2[k];
#pragma unroll
        for (int c = 0; c < 16; c++) s += part[(p * 16 + c) * 7 + k];
        rend[((size_t)b * CCH + k) * NPTS + p0 + p] = s;
    }
}

extern "C" void kernel_launch(void* const* d_in, const int* in_sizes, int n_in,
                              void* d_out, int out_size) {
    (void)in_sizes; (void)n_in; (void)out_size;
    const float* fine     = (const float*)d_in[0];
    const float* coarse   = (const float*)d_in[1];
    const float* w1       = (const float*)d_in[2];
    const float* b1       = (const float*)d_in[3];
    const float* w2       = (const float*)d_in[4];
    const float* b2       = (const float*)d_in[5];
    const float* over_gen = (const float*)d_in[6];
    const float* coverage = (const float*)d_in[7];

    float* rend = (float*)d_out;                 // [16][7][1024]
    float* pts  = rend + NB * CCH * NPTS;        // [16][1024][2]

    cudaFuncSetAttribute(k_select, cudaFuncAttributeMaxDynamicSharedMemorySize, SEL_SMEM);
    cudaFuncSetAttribute(k_gemm,   cudaFuncAttributeMaxDynamicSharedMemorySize, GM_TOT * 4);

    k_top2<<<(NB * CW * CW) / 256, 256>>>(coarse);
    k_unc<<<(NB * NOVER) / 256, 256>>>(over_gen);
    k_select<<<NB, 1024, SEL_SMEM>>>(over_gen, coverage, pts);
    k_gather_coarse<<<(NB * NPTS) / 256, 256>>>(coarse, pts);
    k_gather_fine<<<(NB * NPTS * 16) / 256, 256>>>(fine, pts);
    k_gemm<<<NB * 16, 256, GM_TOT * 4>>>(w1, b1, w2, b2, rend);
}

// round 6
// speedup vs baseline: 1.4111x; 1.2131x over previous
#include <cuda_runtime.h>
#include <stdint.h>

#define NB    16
#define CCH   7
#define FCH   128
#define CW    64
#define FW    256
#define NPTS  1024
#define NIMP  768
#define NCOV  256
#define NOVER 7168
#define HID   256
#define FEATC 135
#define FSTR  136   // feat row stride: fine[0..127], coarse[128..134], pad

typedef unsigned long long ull;

// scratch (no cudaMalloc allowed)
__device__ float g_feat[NB * NPTS * FSTR];

struct BL {
    int   i00, i01, i10, i11;
    float m00, m01, m10, m11;
    float wx, wy;
};

// Replicates the reference's point_sample coordinate math with explicit
// rounding (no FMA contraction) so the top-k selection is bit-stable.
__device__ __forceinline__ void bl_setup(float px, float py, int W, BL& o) {
    float gx = __fsub_rn(__fmul_rn(2.0f, px), 1.0f);
    float gy = __fsub_rn(__fmul_rn(2.0f, py), 1.0f);
    float x  = __fmul_rn(__fsub_rn(__fmul_rn(__fadd_rn(gx, 1.0f), (float)W), 1.0f), 0.5f);
    float y  = __fmul_rn(__fsub_rn(__fmul_rn(__fadd_rn(gy, 1.0f), (float)W), 1.0f), 0.5f);
    float x0f = floorf(x), y0f = floorf(y);
    o.wx = __fsub_rn(x, x0f);
    o.wy = __fsub_rn(y, y0f);
    float x1f = __fadd_rn(x0f, 1.0f), y1f = __fadd_rn(y0f, 1.0f);
    float wm1 = (float)(W - 1);
    bool vx0 = (x0f >= 0.0f) && (x0f <= wm1);
    bool vx1 = (x1f >= 0.0f) && (x1f <= wm1);
    bool vy0 = (y0f >= 0.0f) && (y0f <= wm1);
    bool vy1 = (y1f >= 0.0f) && (y1f <= wm1);
    int ix0 = min(max((int)x0f, 0), W - 1);
    int ix1 = min(max((int)x1f, 0), W - 1);
    int iy0 = min(max((int)y0f, 0), W - 1);
    int iy1 = min(max((int)y1f, 0), W - 1);
    o.i00 = iy0 * W + ix0; o.i01 = iy0 * W + ix1;
    o.i10 = iy1 * W + ix0; o.i11 = iy1 * W + ix1;
    o.m00 = (vx0 && vy0) ? 1.0f : 0.0f;
    o.m01 = (vx1 && vy0) ? 1.0f : 0.0f;
    o.m10 = (vx0 && vy1) ? 1.0f : 0.0f;
    o.m11 = (vx1 && vy1) ? 1.0f : 0.0f;
}

__device__ __forceinline__ float bl_sample(const float* __restrict__ plane, const BL& o) {
    float v00 = __fmul_rn(plane[o.i00], o.m00);
    float v01 = __fmul_rn(plane[o.i01], o.m01);
    float v10 = __fmul_rn(plane[o.i10], o.m10);
    float v11 = __fmul_rn(plane[o.i11], o.m11);
    float owx = __fsub_rn(1.0f, o.wx), owy = __fsub_rn(1.0f, o.wy);
    float t0 = __fmul_rn(__fmul_rn(v00, owx),  owy);
    float t1 = __fmul_rn(__fmul_rn(v01, o.wx), owy);
    float t2 = __fmul_rn(__fmul_rn(v10, owx),  o.wy);
    float t3 = __fmul_rn(__fmul_rn(v11, o.wx), o.wy);
    return __fadd_rn(__fadd_rn(__fadd_rn(t0, t1), t2), t3);
}

// ───────────────────────── k_prep ─────────────────────────
// One block per batch. top2 planes -> smem, uncertainty keys -> smem,
// exact stable top-768 via 6x8-bit radix-select (parallel scan),
// compact + 1024-key bitonic sort, emit points.
// smem bytes: st2 32768 | keys 57344 | buf 8192 | hist 1024 | scan 1024 | ctrl 32
#define PR_ST2   0
#define PR_KEYS  32768
#define PR_BUF   90112
#define PR_HIST  98304
#define PR_SCAN  99328
#define PR_CTRL  100352
#define PR_SMEM  100384

__global__ void __launch_bounds__(1024) k_prep(const float* __restrict__ coarse,
                                               const float* __restrict__ over_gen,
                                               const float* __restrict__ coverage,
                                               float* __restrict__ pts_out) {
    extern __shared__ char smraw[];
    float*    st2  = (float*)(smraw + PR_ST2);
    ull*      keys = (ull*)(smraw + PR_KEYS);
    ull*      buf  = (ull*)(smraw + PR_BUF);
    unsigned* hist = (unsigned*)(smraw + PR_HIST);
    unsigned* scan = (unsigned*)(smraw + PR_SCAN);
    ull*      s_prefix = (ull*)(smraw + PR_CTRL);
    int*      s_rank   = (int*)(smraw + PR_CTRL + 8);
    int*      s_cnt    = (int*)(smraw + PR_CTRL + 12);

    int b = blockIdx.x;
    int t = threadIdx.x;

    // top-2 over 7 channels, into smem
    const float* cb = coarse + (size_t)b * CCH * 4096;
    for (int pix = t; pix < 4096; pix += 1024) {
        float m1 = __int_as_float(0xff800000), m2 = m1;
#pragma unroll
        for (int c = 0; c < CCH; c++) {
            float v = cb[c * 4096 + pix];
            if (v > m1) { m2 = m1; m1 = v; }
            else if (v > m2) { m2 = v; }
        }
        st2[pix]        = m1;
        st2[4096 + pix] = m2;
    }
    if (t == 0) { *s_prefix = 0ull; *s_rank = NIMP; *s_cnt = 0; }
    __syncthreads();

    // uncertainty + composite keys
    const float2* og = (const float2*)over_gen + (size_t)b * NOVER;
    for (int i = t; i < NOVER; i += 1024) {
        float2 p = og[i];
        BL o;
        bl_setup(p.x, p.y, CW, o);
        float s0 = bl_sample(st2, o);
        float s1 = bl_sample(st2 + 4096, o);
        float un = -__fsub_rn(s0, s1);
        unsigned u = __float_as_uint(un);
        u = (u & 0x80000000u) ? ~u : (u ^ 0x80000000u);  // order-preserving
        keys[i] = ((ull)(~u) << 13) | (unsigned)i;       // desc value, asc idx
    }
    __syncthreads();

    // radix-select: 6 byte passes, MSB->LSB
    for (int byte = 5; byte >= 0; byte--) {
        int shift = byte * 8;
        ull pref = *s_prefix;
        int rank = *s_rank;
        if (t < 256) hist[t] = 0;
        __syncthreads();
        for (int i = t; i < NOVER; i += 1024) {
            ull k = keys[i];
            if ((k >> (shift + 8)) == pref)
                atomicAdd(&hist[(unsigned)(k >> shift) & 255u], 1u);
        }
        __syncthreads();
        if (t < 256) scan[t] = hist[t];
        __syncthreads();
        for (int off = 1; off < 256; off <<= 1) {
            unsigned v = 0;
            if (t < 256) { v = scan[t]; if (t >= off) v += scan[t - off]; }
            __syncthreads();
            if (t < 256) scan[t] = v;
            __syncthreads();
        }
        if (t < 256) {
            unsigned incl = scan[t], excl = incl - hist[t];
            if (excl < (unsigned)rank && (unsigned)rank <= incl) {
                *s_rank   = rank - (int)excl;
                *s_prefix = (pref << 8) | (unsigned)t;
            }
        }
        __syncthreads();
    }

    // compact the exact 768 winners (keys unique => exactly NIMP of them)
    ull kstar = *s_prefix;
    for (int i = t; i < NOVER; i += 1024) {
        ull k = keys[i];
        if (k <= kstar) {
            int pos = atomicAdd(s_cnt, 1);
            buf[pos] = k;
        }
    }
    if (t >= NIMP) buf[t] = ~0ull;
    __syncthreads();

    // bitonic sort 1024 keys (one per thread)
    for (unsigned k = 2; k <= 1024; k <<= 1) {
        for (unsigned j = k >> 1; j > 0; j >>= 1) {
            unsigned i = t, ixj = i ^ j;
            if (ixj > i) {
                ull a = buf[i], c = buf[ixj];
                bool up = ((i & k) == 0);
                if ((a > c) == up) { buf[i] = c; buf[ixj] = a; }
            }
            __syncthreads();
        }
    }

    float* dst = pts_out + (size_t)b * NPTS * 2;
    if (t < NIMP) {
        int n = (int)(buf[t] & 0x1FFFull);
        float2 p = og[n];
        dst[t * 2 + 0] = p.x;
        dst[t * 2 + 1] = p.y;
    } else {
        int i = t - NIMP;
        float2 p = ((const float2*)coverage)[(size_t)b * NCOV + i];
        dst[(NIMP + i) * 2 + 0] = p.x;
        dst[(NIMP + i) * 2 + 1] = p.y;
    }
}

// ───────────────────────── k_gather ─────────────────────────
// fine: one thread per (b,p,cg8) -> 8 channels. coarse: one thread per (b,p).
#define FINE_THREADS (NB * NPTS * 16)
#define GATH_THREADS (FINE_THREADS + NB * NPTS)

__global__ void k_gather(const float* __restrict__ fine,
                         const float* __restrict__ coarse,
                         const float* __restrict__ pts) {
    int id = blockIdx.x * blockDim.x + threadIdx.x;
    if (id < FINE_THREADS) {
        int cg = id & 15;
        int bp = id >> 4;
        int b  = bp >> 10;
        float2 p = ((const float2*)pts)[bp];
        BL o;
        bl_setup(p.x, p.y, FW, o);
        float owx = 1.0f - o.wx, owy = 1.0f - o.wy;
        float w00 = owx * owy, w01 = o.wx * owy, w10 = owx * o.wy, w11 = o.wx * o.wy;
        const float* base = fine + ((size_t)b * FCH + cg * 8) * 65536;
        float v[8];
#pragma unroll
        for (int j = 0; j < 8; j++) {
            const float* pl = base + (size_t)j * 65536;
            v[j] = pl[o.i00] * o.m00 * w00 + pl[o.i01] * o.m01 * w01
                 + pl[o.i10] * o.m10 * w10 + pl[o.i11] * o.m11 * w11;
        }
        float* dst = g_feat + (size_t)bp * FSTR + cg * 8;
        *(float4*)(dst)     = make_float4(v[0], v[1], v[2], v[3]);
        *(float4*)(dst + 4) = make_float4(v[4], v[5], v[6], v[7]);
    } else {
        int bp = id - FINE_THREADS;   // 0..16383
        int b  = bp >> 10;
        float2 p = ((const float2*)pts)[bp];
        BL o;
        bl_setup(p.x, p.y, CW, o);
        float owx = 1.0f - o.wx, owy = 1.0f - o.wy;
        float w00 = owx * owy, w01 = o.wx * owy, w10 = owx * o.wy, w11 = o.wx * o.wy;
        const float* base = coarse + (size_t)b * CCH * 4096;
        float* dst = g_feat + (size_t)bp * FSTR + FCH;
#pragma unroll
        for (int c = 0; c < CCH; c++) {
            const float* pl = base + c * 4096;
            dst[c] = pl[o.i00] * o.m00 * w00 + pl[o.i01] * o.m01 * w01
                   + pl[o.i10] * o.m10 * w10 + pl[o.i11] * o.m11 * w11;
        }
    }
}

// ───────────────────────── k_gemm ─────────────────────────
// 512 CTAs x 32 points, 256 threads, thread tile 2 pts x 16 cols.
// w1s padded (groups of 16 stored at stride 20 floats) -> conflict-free LDS.128.
// smem floats: sf 4352 | w1s 8640 (reused as part 3584) | w2s 1792
#define GM_SF   0
#define GM_W1S  4352
#define GM_W2S  12992
#define GM_TOT  14784   // floats -> 59136 bytes

__global__ void __launch_bounds__(256) k_gemm(
    const float* __restrict__ w1, const float* __restrict__ b1,
    const float* __restrict__ w2, const float* __restrict__ b2,
    float* __restrict__ rend)
{
    extern __shared__ float sm[];
    float* sf   = sm + GM_SF;
    float* w1s  = sm + GM_W1S;
    float* w2s  = sm + GM_W2S;
    float* part = sm + GM_W1S;  // reused after GEMM1

    int t   = threadIdx.x;
    int bp0 = blockIdx.x * 32;          // global point base
    int b   = bp0 >> 10;
    int cg  = t & 15;                   // col group (16 cols)
    int pg  = t >> 4;                   // point group (2 pts)

    // stage feat tile [32][136] (rows contiguous in g_feat) and w2
    const float4* gsrc = (const float4*)(g_feat + (size_t)bp0 * FSTR);
    for (int i = t; i < 32 * FSTR / 4; i += 256) ((float4*)sf)[i] = gsrc[i];
    for (int i = t; i < HID * 7; i += 256) w2s[i] = w2[i];

    float acc[2][16];
#pragma unroll
    for (int j = 0; j < 16; j++) {
        float bv = b1[cg * 16 + j];
        acc[0][j] = bv; acc[1][j] = bv;
    }
    __syncthreads();

    // GEMM1: 5 k-chunks of 27 over 135.
    // feat k<128 -> w1 row 7+k (fine), k>=128 -> row k-128 (coarse)
    for (int c5 = 0; c5 < 5; c5++) {
        int k0 = c5 * 27;
        if (c5) __syncthreads();
        for (int i = t; i < 27 * HID; i += 256) {
            int kk = i >> 8, c = i & 255;
            int row = k0 + kk;
            int srow = (row < FCH) ? (CCH + row) : (row - FCH);
            w1s[kk * 320 + (c >> 4) * 20 + (c & 15)] = w1[srow * HID + c];
        }
        __syncthreads();
        const float* f0p = &sf[(pg * 2 + 0) * FSTR + k0];
        const float* f1p = &sf[(pg * 2 + 1) * FSTR + k0];
#pragma unroll 3
        for (int kk = 0; kk < 27; kk++) {
            float f0 = f0p[kk];
            float f1 = f1p[kk];
            const float* wr = &w1s[kk * 320 + cg * 20];
#pragma unroll
            for (int q = 0; q < 4; q++) {
                float4 w = *(const float4*)(wr + q * 4);
                acc[0][q*4+0] += f0 * w.x; acc[0][q*4+1] += f0 * w.y;
                acc[0][q*4+2] += f0 * w.z; acc[0][q*4+3] += f0 * w.w;
                acc[1][q*4+0] += f1 * w.x; acc[1][q*4+1] += f1 * w.y;
                acc[1][q*4+2] += f1 * w.z; acc[1][q*4+3] += f1 * w.w;
            }
        }
    }
    __syncthreads();  // done with w1s; reuse as part

    // GEMM2 partials: relu(acc) * w2 over this thread's 16 d's
#pragma unroll
    for (int i = 0; i < 2; i++) {
        float pr[7];
#pragma unroll
        for (int k = 0; k < 7; k++) pr[k] = 0.0f;
#pragma unroll
        for (int j = 0; j < 16; j++) {
            float hv = fmaxf(acc[i][j], 0.0f);
            const float* wr = &w2s[(cg * 16 + j) * 7];
#pragma unroll
            for (int k = 0; k < 7; k++) pr[k] += hv * wr[k];
        }
        float* pp = &part[((pg * 2 + i) * 16 + cg) * 7];
#pragma unroll
        for (int k = 0; k < 7; k++) pp[k] = pr[k];
    }
    __syncthreads();

    // reduce across 16 col groups, add b2, write rend[b][k][p]
    for (int task = t; task < 32 * 7; task += 256) {
        int p = task / 7, k = task % 7;
        float s = b2[k];
#pragma unroll
        for (int c = 0; c < 16; c++) s += part[(p * 16 + c) * 7 + k];
        rend[((size_t)b * CCH + k) * NPTS + (bp0 & 1023) + p] = s;
    }
}

extern "C" void kernel_launch(void* const* d_in, const int* in_sizes, int n_in,
                              void* d_out, int out_size) {
    (void)in_sizes; (void)n_in; (void)out_size;
    const float* fine     = (const float*)d_in[0];
    const float* coarse   = (const float*)d_in[1];
    const float* w1       = (const float*)d_in[2];
    const float* b1       = (const float*)d_in[3];
    const float* w2       = (const float*)d_in[4];
    const float* b2       = (const float*)d_in[5];
    const float* over_gen = (const float*)d_in[6];
    const float* coverage = (const float*)d_in[7];

    float* rend = (float*)d_out;                 // [16][7][1024]
    float* pts  = rend + NB * CCH * NPTS;        // [16][1024][2]

    cudaFuncSetAttribute(k_prep, cudaFuncAttributeMaxDynamicSharedMemorySize, PR_SMEM);
    cudaFuncSetAttribute(k_gemm, cudaFuncAttributeMaxDynamicSharedMemorySize, GM_TOT * 4);

    k_prep<<<NB, 1024, PR_SMEM>>>(coarse, over_gen, coverage, pts);
    k_gather<<<GATH_THREADS / 256, 256>>>(fine, coarse, pts);
    k_gemm<<<NB * 32, 256, GM_TOT * 4>>>(w1, b1, w2, b2, rend);
}

// round 7
// speedup vs baseline: 1.9690x; 1.3953x over previous
#include <cuda_runtime.h>
#include <stdint.h>

#define NB    16
#define CCH   7
#define FCH   128
#define CW    64
#define FW    256
#define NPTS  1024
#define NIMP  768
#define NCOV  256
#define NOVER 7168
#define HID   256
#define FEATC 135

typedef unsigned long long ull;

// ───────────────────────── helpers ─────────────────────────

__device__ __forceinline__ ull fma2(ull a, ull b, ull c) {
    ull d;
    asm("fma.rn.f32x2 %0, %1, %2, %3;" : "=l"(d) : "l"(a), "l"(b), "l"(c));
    return d;
}
__device__ __forceinline__ ull pack2(float lo, float hi) {
    ull d;
    asm("mov.b64 %0, {%1, %2};" : "=l"(d) : "f"(lo), "f"(hi));
    return d;
}
__device__ __forceinline__ void unpack2(ull v, float& lo, float& hi) {
    asm("mov.b64 {%0, %1}, %2;" : "=f"(lo), "=f"(hi) : "l"(v));
}
__device__ __forceinline__ void cp_async16(void* dst, const void* src) {
    unsigned d = (unsigned)__cvta_generic_to_shared(dst);
    asm volatile("cp.async.ca.shared.global [%0], [%1], 16;\n" :: "r"(d), "l"(src));
}
#define CP_COMMIT() asm volatile("cp.async.commit_group;\n" ::: "memory")
#define CP_WAIT0()  asm volatile("cp.async.wait_group 0;\n" ::: "memory")

struct BL {
    int   i00, i01, i10, i11;
    float m00, m01, m10, m11;
    float wx, wy;
};

// Replicates the reference's point_sample coordinate math with explicit
// rounding (no FMA contraction) so the top-k selection is bit-stable.
__device__ __forceinline__ void bl_setup(float px, float py, int W, BL& o) {
    float gx = __fsub_rn(__fmul_rn(2.0f, px), 1.0f);
    float gy = __fsub_rn(__fmul_rn(2.0f, py), 1.0f);
    float x  = __fmul_rn(__fsub_rn(__fmul_rn(__fadd_rn(gx, 1.0f), (float)W), 1.0f), 0.5f);
    float y  = __fmul_rn(__fsub_rn(__fmul_rn(__fadd_rn(gy, 1.0f), (float)W), 1.0f), 0.5f);
    float x0f = floorf(x), y0f = floorf(y);
    o.wx = __fsub_rn(x, x0f);
    o.wy = __fsub_rn(y, y0f);
    float x1f = __fadd_rn(x0f, 1.0f), y1f = __fadd_rn(y0f, 1.0f);
    float wm1 = (float)(W - 1);
    bool vx0 = (x0f >= 0.0f) && (x0f <= wm1);
    bool vx1 = (x1f >= 0.0f) && (x1f <= wm1);
    bool vy0 = (y0f >= 0.0f) && (y0f <= wm1);
    bool vy1 = (y1f >= 0.0f) && (y1f <= wm1);
    int ix0 = min(max((int)x0f, 0), W - 1);
    int ix1 = min(max((int)x1f, 0), W - 1);
    int iy0 = min(max((int)y0f, 0), W - 1);
    int iy1 = min(max((int)y1f, 0), W - 1);
    o.i00 = iy0 * W + ix0; o.i01 = iy0 * W + ix1;
    o.i10 = iy1 * W + ix0; o.i11 = iy1 * W + ix1;
    o.m00 = (vx0 && vy0) ? 1.0f : 0.0f;
    o.m01 = (vx1 && vy0) ? 1.0f : 0.0f;
    o.m10 = (vx0 && vy1) ? 1.0f : 0.0f;
    o.m11 = (vx1 && vy1) ? 1.0f : 0.0f;
}

__device__ __forceinline__ float bl_sample(const float* __restrict__ plane, const BL& o) {
    float v00 = __fmul_rn(plane[o.i00], o.m00);
    float v01 = __fmul_rn(plane[o.i01], o.m01);
    float v10 = __fmul_rn(plane[o.i10], o.m10);
    float v11 = __fmul_rn(plane[o.i11], o.m11);
    float owx = __fsub_rn(1.0f, o.wx), owy = __fsub_rn(1.0f, o.wy);
    float t0 = __fmul_rn(__fmul_rn(v00, owx),  owy);
    float t1 = __fmul_rn(__fmul_rn(v01, o.wx), owy);
    float t2 = __fmul_rn(__fmul_rn(v10, owx),  o.wy);
    float t3 = __fmul_rn(__fmul_rn(v11, o.wx), o.wy);
    return __fadd_rn(__fadd_rn(__fadd_rn(t0, t1), t2), t3);
}

// ───────────────────────── k_prep ─────────────────────────
// One block per batch. top2 -> smem, keys -> smem, early-exit radix select
// (pass 1 scans all 7168 keys, later passes scan only the shrinking candidate
// bin), union(definite winners, candidates) <= 1024 -> bitonic sort -> points.
#define PR_ST2   0
#define PR_KEYS  32768
#define PR_CAND  90112
#define PR_BUF   147456
#define PR_HIST  155648
#define PR_SCAN  156672
#define PR_CTRL  157696
#define PR_SMEM  157728

__global__ void __launch_bounds__(1024) k_prep(const float* __restrict__ coarse,
                                               const float* __restrict__ over_gen,
                                               const float* __restrict__ coverage,
                                               float* __restrict__ pts_out) {
    extern __shared__ char smraw[];
    float*    st2  = (float*)(smraw + PR_ST2);
    ull*      keys = (ull*)(smraw + PR_KEYS);
    ull*      cand = (ull*)(smraw + PR_CAND);
    ull*      buf  = (ull*)(smraw + PR_BUF);
    unsigned* hist = (unsigned*)(smraw + PR_HIST);
    unsigned* scan = (unsigned*)(smraw + PR_SCAN);
    int*      s_sel  = (int*)(smraw + PR_CTRL);
    int*      s_rank = (int*)(smraw + PR_CTRL + 4);
    int*      s_wcnt = (int*)(smraw + PR_CTRL + 8);
    int*      s_ccnt = (int*)(smraw + PR_CTRL + 12);

    int b = blockIdx.x;
    int t = threadIdx.x;

    // top-2 over 7 channels, into smem
    const float* cb = coarse + (size_t)b * CCH * 4096;
    for (int pix = t; pix < 4096; pix += 1024) {
        float m1 = __int_as_float(0xff800000), m2 = m1;
#pragma unroll
        for (int c = 0; c < CCH; c++) {
            float v = cb[c * 4096 + pix];
            if (v > m1) { m2 = m1; m1 = v; }
            else if (v > m2) { m2 = v; }
        }
        st2[pix]        = m1;
        st2[4096 + pix] = m2;
    }
    if (t == 0) { *s_wcnt = 0; }
    __syncthreads();

    // uncertainty + composite keys (value desc via order-mapped ~bits, idx asc)
    const float2* og = (const float2*)over_gen + (size_t)b * NOVER;
    for (int i = t; i < NOVER; i += 1024) {
        float2 p = og[i];
        BL o;
        bl_setup(p.x, p.y, CW, o);
        float s0 = bl_sample(st2, o);
        float s1 = bl_sample(st2 + 4096, o);
        float un = -__fsub_rn(s0, s1);
        unsigned u = __float_as_uint(un);
        u = (u & 0x80000000u) ? ~u : (u ^ 0x80000000u);
        keys[i] = ((ull)(~u) << 13) | (unsigned)i;
    }
    __syncthreads();

    // early-exit radix select
    ull* src = keys;
    ull* dstc = cand;
    int m = NOVER;
    int rank = NIMP;
    int total = 0;
    for (int byte = 5; byte >= 0; byte--) {
        int sh = byte * 8;
        if (t < 256) hist[t] = 0;
        __syncthreads();
        for (int i = t; i < m; i += 1024)
            atomicAdd(&hist[(unsigned)(src[i] >> sh) & 255u], 1u);
        __syncthreads();
        if (t < 256) scan[t] = hist[t];
        __syncthreads();
        for (int off = 1; off < 256; off <<= 1) {
            unsigned v = 0;
            if (t < 256) { v = scan[t]; if (t >= off) v += scan[t - off]; }
            __syncthreads();
            if (t < 256) scan[t] = v;
            __syncthreads();
        }
        if (t < 256) {
            unsigned incl = scan[t], excl = incl - hist[t];
            if (excl < (unsigned)rank && (unsigned)rank <= incl) {
                *s_sel  = t;
                *s_rank = rank - (int)excl;
            }
        }
        if (t == 0) *s_ccnt = 0;
        __syncthreads();
        int sel = *s_sel;
        rank = *s_rank;
        // partition: digit<sel -> definite winner; ==sel -> candidate
        for (int i = t; i < m; i += 1024) {
            ull k = src[i];
            int d = (int)((unsigned)(k >> sh) & 255u);
            if (d < sel)       buf[atomicAdd(s_wcnt, 1)] = k;
            else if (d == sel) dstc[atomicAdd(s_ccnt, 1)] = k;
        }
        __syncthreads();
        m = *s_ccnt;
        int w = *s_wcnt;
        if (w + m <= 1024) {
            for (int i = t; i < m; i += 1024) buf[w + i] = dstc[i];
            total = w + m;
            break;
        }
        ull* tmp = src; src = dstc; dstc = tmp;
        __syncthreads();
    }
    __syncthreads();
    // pad to 1024 and bitonic sort; first 768 = stable top-k
    if (t >= total) buf[t] = ~0ull;
    __syncthreads();
    for (unsigned k = 2; k <= 1024; k <<= 1) {
        for (unsigned j = k >> 1; j > 0; j >>= 1) {
            unsigned i = t, ixj = i ^ j;
            if (ixj > i) {
                ull a = buf[i], c = buf[ixj];
                bool up = ((i & k) == 0);
                if ((a > c) == up) { buf[i] = c; buf[ixj] = a; }
            }
            __syncthreads();
        }
    }

    float* dst = pts_out + (size_t)b * NPTS * 2;
    if (t < NIMP) {
        int n = (int)(buf[t] & 0x1FFFull);
        float2 p = og[n];
        dst[t * 2 + 0] = p.x;
        dst[t * 2 + 1] = p.y;
    } else {
        int i = t - NIMP;
        float2 p = ((const float2*)coverage)[(size_t)b * NCOV + i];
        dst[(NIMP + i) * 2 + 0] = p.x;
        dst[(NIMP + i) * 2 + 1] = p.y;
    }
}

// ───────────────────────── k_fused ─────────────────────────
// 512 CTAs x 32 points. Pipelined: gather chunk c+1 (LDG in regs) + cp.async
// w1 chunk c overlap the packed-f32x2 GEMM on chunk c. Epilogue: relu + w2.
// Feat rows: 0..127 fine, 128..134 coarse; w1 srow = row<128 ? 7+row : row-128.
// smem floats: sfb 2*891 | w1s 8640 (stride 20 pad; reused as part) | w2s 1792 | BL 640
#define FU_SFB   0
#define FU_W1S   1792
#define FU_W2S   10432
#define FU_CBL   12224
#define FU_TOT   12864   // floats -> 51456 bytes

#define CHK  27
#define SFS  33          // sfb row stride

__global__ void __launch_bounds__(256, 2) k_fused(
    const float* __restrict__ fine, const float* __restrict__ coarse,
    const float* __restrict__ w1, const float* __restrict__ b1,
    const float* __restrict__ w2, const float* __restrict__ b2,
    const float* __restrict__ pts, float* __restrict__ rend)
{
    extern __shared__ float sm[];
    float* sfb = sm + FU_SFB;       // [2][27*33]
    float* w1s = sm + FU_W1S;       // [27][320] (16-col groups at stride 20)
    float* w2s = sm + FU_W2S;       // [256][7]
    float* cbl = sm + FU_CBL;
    int*   fi  = (int*)cbl;         // [4][32] fine idx
    float* fm  = cbl + 128;         // [4][32] fine mask
    float* fwx = cbl + 256;         // [32]
    float* fwy = cbl + 288;
    int*   ci  = (int*)(cbl + 320); // [4][32] coarse idx
    float* cm  = cbl + 448;
    float* cwx = cbl + 576;
    float* cwy = cbl + 608;
    float* part = w1s;              // reused after GEMM1

    int t   = threadIdx.x;
    int bp0 = blockIdx.x * 32;
    int b   = bp0 >> 10;
    int cg  = t & 15;
    int pg  = t >> 4;

    // prologue: BLs for 32 points (fine by t<32, coarse by t in [32,64))
    if (t < 32) {
        float2 p = ((const float2*)pts)[bp0 + t];
        BL o;
        bl_setup(p.x, p.y, FW, o);
        fi[0*32+t] = o.i00; fi[1*32+t] = o.i01; fi[2*32+t] = o.i10; fi[3*32+t] = o.i11;
        fm[0*32+t] = o.m00; fm[1*32+t] = o.m01; fm[2*32+t] = o.m10; fm[3*32+t] = o.m11;
        fwx[t] = o.wx; fwy[t] = o.wy;
    } else if (t < 64) {
        int p_ = t - 32;
        float2 p = ((const float2*)pts)[bp0 + p_];
        BL o;
        bl_setup(p.x, p.y, CW, o);
        ci[0*32+p_] = o.i00; ci[1*32+p_] = o.i01; ci[2*32+p_] = o.i10; ci[3*32+p_] = o.i11;
        cm[0*32+p_] = o.m00; cm[1*32+p_] = o.m01; cm[2*32+p_] = o.m10; cm[3*32+p_] = o.m11;
        cwx[p_] = o.wx; cwy[p_] = o.wy;
    }
    for (int i = t; i < HID * 7; i += 256) w2s[i] = w2[i];

    // accumulators: 2 pts x 16 cols as 2x8 packed f32x2, init with bias
    ull acc2[2][8];
#pragma unroll
    for (int j = 0; j < 8; j++) {
        ull bv = pack2(b1[cg * 16 + 2 * j], b1[cg * 16 + 2 * j + 1]);
        acc2[0][j] = bv; acc2[1][j] = bv;
    }
    __syncthreads();

    float gv[4][4];

    // gather chunk 0
    {
        int k0 = 0;
#pragma unroll
        for (int s = 0; s < 4; s++) {
            int task = s * 256 + t;
            if (task < 32 * CHK) {
                int kk = task >> 5, p = task & 31;
                int ch = k0 + kk;
                const float* pl = fine + ((size_t)b * FCH + ch) * 65536;
                gv[s][0] = pl[fi[0*32+p]]; gv[s][1] = pl[fi[1*32+p]];
                gv[s][2] = pl[fi[2*32+p]]; gv[s][3] = pl[fi[3*32+p]];
            }
        }
#pragma unroll
        for (int s = 0; s < 4; s++) {
            int task = s * 256 + t;
            if (task < 32 * CHK) {
                int kk = task >> 5, p = task & 31;
                float wx = fwx[p], wy = fwy[p];
                float owx = 1.0f - wx, owy = 1.0f - wy;
                float v = gv[s][0] * fm[0*32+p] * (owx*owy) + gv[s][1] * fm[1*32+p] * (wx*owy)
                        + gv[s][2] * fm[2*32+p] * (owx*wy)  + gv[s][3] * fm[3*32+p] * (wx*wy);
                sfb[kk * SFS + p] = v;
            }
        }
    }

    for (int c = 0; c < 5; c++) {
        __syncthreads();   // sfb[c&1] visible; prior compute done -> w1s free
        int k0 = c * CHK;
        // cp.async w1 chunk c into padded layout
        for (int i = t; i < CHK * 64; i += 256) {
            int kk = i >> 6, seg = i & 63;
            int g = seg >> 2, q = seg & 3;
            int row = k0 + kk;
            int srow = (row < FCH) ? (CCH + row) : (row - FCH);
            cp_async16(&w1s[kk * 320 + g * 20 + q * 4],
                       w1 + (size_t)srow * HID + g * 16 + q * 4);
        }
        CP_COMMIT();
        // issue gather LDGs for chunk c+1
        if (c < 4) {
            int k1 = (c + 1) * CHK;
#pragma unroll
            for (int s = 0; s < 4; s++) {
                int task = s * 256 + t;
                if (task < 32 * CHK) {
                    int kk = task >> 5, p = task & 31;
                    int ch = k1 + kk;
                    if (ch < FCH) {
                        const float* pl = fine + ((size_t)b * FCH + ch) * 65536;
                        gv[s][0] = pl[fi[0*32+p]]; gv[s][1] = pl[fi[1*32+p]];
                        gv[s][2] = pl[fi[2*32+p]]; gv[s][3] = pl[fi[3*32+p]];
                    } else {
                        const float* pl = coarse + ((size_t)b * CCH + (ch - FCH)) * 4096;
                        gv[s][0] = pl[ci[0*32+p]]; gv[s][1] = pl[ci[1*32+p]];
                        gv[s][2] = pl[ci[2*32+p]]; gv[s][3] = pl[ci[3*32+p]];
                    }
                }
            }
        }
        CP_WAIT0();
        __syncthreads();   // w1s chunk c ready for all threads

        // compute chunk c: packed f32x2 FMA
        const float* sb = sfb + (c & 1) * (CHK * SFS);
#pragma unroll 3
        for (int kk = 0; kk < CHK; kk++) {
            float f0 = sb[kk * SFS + 2 * pg];
            float f1 = sb[kk * SFS + 2 * pg + 1];
            ull ff0 = pack2(f0, f0);
            ull ff1 = pack2(f1, f1);
            const float* wr = &w1s[kk * 320 + cg * 20];
#pragma unroll
            for (int q = 0; q < 4; q++) {
                ulonglong2 w = *(const ulonglong2*)(wr + q * 4);
                acc2[0][2*q]   = fma2(w.x, ff0, acc2[0][2*q]);
                acc2[0][2*q+1] = fma2(w.y, ff0, acc2[0][2*q+1]);
                acc2[1][2*q]   = fma2(w.x, ff1, acc2[1][2*q]);
                acc2[1][2*q+1] = fma2(w.y, ff1, acc2[1][2*q+1]);
            }
        }

        // combine + store gathered chunk c+1 into other buffer
        if (c < 4) {
            int k1 = (c + 1) * CHK;
            float* so = sfb + ((c + 1) & 1) * (CHK * SFS);
#pragma unroll
            for (int s = 0; s < 4; s++) {
                int task = s * 256 + t;
                if (task < 32 * CHK) {
                    int kk = task >> 5, p = task & 31;
                    int ch = k1 + kk;
                    float wx, wy, m0, m1, m2, m3;
                    if (ch < FCH) {
                        wx = fwx[p]; wy = fwy[p];
                        m0 = fm[0*32+p]; m1 = fm[1*32+p]; m2 = fm[2*32+p]; m3 = fm[3*32+p];
                    } else {
                        wx = cwx[p]; wy = cwy[p];
                        m0 = cm[0*32+p]; m1 = cm[1*32+p]; m2 = cm[2*32+p]; m3 = cm[3*32+p];
                    }
                    float owx = 1.0f - wx, owy = 1.0f - wy;
                    float v = gv[s][0] * m0 * (owx*owy) + gv[s][1] * m1 * (wx*owy)
                            + gv[s][2] * m2 * (owx*wy)  + gv[s][3] * m3 * (wx*wy);
                    so[kk * SFS + p] = v;
                }
            }
        }
    }
    __syncthreads();   // all compute done; w1s free -> reuse as part

    // GEMM2 partials: relu(acc) * w2 over this thread's 16 d's
#pragma unroll
    for (int i = 0; i < 2; i++) {
        float pr[7];
#pragma unroll
        for (int k = 0; k < 7; k++) pr[k] = 0.0f;
#pragma unroll
        for (int j = 0; j < 8; j++) {
            float h0, h1;
            unpack2(acc2[i][j], h0, h1);
            h0 = fmaxf(h0, 0.0f); h1 = fmaxf(h1, 0.0f);
            const float* wr0 = &w2s[(cg * 16 + 2 * j) * 7];
            const float* wr1 = wr0 + 7;
#pragma unroll
            for (int k = 0; k < 7; k++) pr[k] += h0 * wr0[k] + h1 * wr1[k];
        }
        float* pp = &part[((pg * 2 + i) * 16 + cg) * 7];
#pragma unroll
        for (int k = 0; k < 7; k++) pp[k] = pr[k];
    }
    __syncthreads();

    // reduce across 16 col groups, add b2, write rend[b][k][p]
    for (int task = t; task < 32 * 7; task += 256) {
        int p = task / 7, k = task % 7;
        float s = b2[k];
#pragma unroll
        for (int c = 0; c < 16; c++) s += part[(p * 16 + c) * 7 + k];
        rend[((size_t)b * CCH + k) * NPTS + (bp0 & 1023) + p] = s;
    }
}

extern "C" void kernel_launch(void* const* d_in, const int* in_sizes, int n_in,
                              void* d_out, int out_size) {
    (void)in_sizes; (void)n_in; (void)out_size;
    const float* fine     = (const float*)d_in[0];
    const float* coarse   = (const float*)d_in[1];
    const float* w1       = (const float*)d_in[2];
    const float* b1       = (const float*)d_in[3];
    const float* w2       = (const float*)d_in[4];
    const float* b2       = (const float*)d_in[5];
    const float* over_gen = (const float*)d_in[6];
    const float* coverage = (const float*)d_in[7];

    float* rend = (float*)d_out;                 // [16][7][1024]
    float* pts  = rend + NB * CCH * NPTS;        // [16][1024][2]

    cudaFuncSetAttribute(k_prep,  cudaFuncAttributeMaxDynamicSharedMemorySize, PR_SMEM);
    cudaFuncSetAttribute(k_fused, cudaFuncAttributeMaxDynamicSharedMemorySize, FU_TOT * 4);

    k_prep<<<NB, 1024, PR_SMEM>>>(coarse, over_gen, coverage, pts);
    k_fused<<<NB * 32, 256, FU_TOT * 4>>>(fine, coarse, w1, b1, w2, b2, pts, rend);
}

// round 8
// speedup vs baseline: 2.3152x; 1.1758x over previous
#include <cuda_runtime.h>
#include <stdint.h>

#define NB    16
#define CCH   7
#define FCH   128
#define CW    64
#define FW    256
#define NPTS  1024
#define NIMP  768
#define NCOV  256
#define NOVER 7168
#define HID   256
#define FEATC 135

typedef unsigned long long ull;

// ───────────────────────── helpers ─────────────────────────

__device__ __forceinline__ ull fma2(ull a, ull b, ull c) {
    ull d;
    asm("fma.rn.f32x2 %0, %1, %2, %3;" : "=l"(d) : "l"(a), "l"(b), "l"(c));
    return d;
}
__device__ __forceinline__ ull pack2(float lo, float hi) {
    ull d;
    asm("mov.b64 %0, {%1, %2};" : "=l"(d) : "f"(lo), "f"(hi));
    return d;
}
__device__ __forceinline__ void unpack2(ull v, float& lo, float& hi) {
    asm("mov.b64 {%0, %1}, %2;" : "=f"(lo), "=f"(hi) : "l"(v));
}
__device__ __forceinline__ void cp_async16(void* dst, const void* src) {
    unsigned d = (unsigned)__cvta_generic_to_shared(dst);
    asm volatile("cp.async.ca.shared.global [%0], [%1], 16;\n" :: "r"(d), "l"(src));
}
#define CP_COMMIT() asm volatile("cp.async.commit_group;\n" ::: "memory")
#define CP_WAIT0()  asm volatile("cp.async.wait_group 0;\n" ::: "memory")

struct BL {
    int   i00, i01, i10, i11;
    float m00, m01, m10, m11;
    float wx, wy;
};

// Replicates the reference's point_sample coordinate math with explicit
// rounding (no FMA contraction) so the top-k selection is bit-stable.
__device__ __forceinline__ void bl_setup(float px, float py, int W, BL& o) {
    float gx = __fsub_rn(__fmul_rn(2.0f, px), 1.0f);
    float gy = __fsub_rn(__fmul_rn(2.0f, py), 1.0f);
    float x  = __fmul_rn(__fsub_rn(__fmul_rn(__fadd_rn(gx, 1.0f), (float)W), 1.0f), 0.5f);
    float y  = __fmul_rn(__fsub_rn(__fmul_rn(__fadd_rn(gy, 1.0f), (float)W), 1.0f), 0.5f);
    float x0f = floorf(x), y0f = floorf(y);
    o.wx = __fsub_rn(x, x0f);
    o.wy = __fsub_rn(y, y0f);
    float x1f = __fadd_rn(x0f, 1.0f), y1f = __fadd_rn(y0f, 1.0f);
    float wm1 = (float)(W - 1);
    bool vx0 = (x0f >= 0.0f) && (x0f <= wm1);
    bool vx1 = (x1f >= 0.0f) && (x1f <= wm1);
    bool vy0 = (y0f >= 0.0f) && (y0f <= wm1);
    bool vy1 = (y1f >= 0.0f) && (y1f <= wm1);
    int ix0 = min(max((int)x0f, 0), W - 1);
    int ix1 = min(max((int)x1f, 0), W - 1);
    int iy0 = min(max((int)y0f, 0), W - 1);
    int iy1 = min(max((int)y1f, 0), W - 1);
    o.i00 = iy0 * W + ix0; o.i01 = iy0 * W + ix1;
    o.i10 = iy1 * W + ix0; o.i11 = iy1 * W + ix1;
    o.m00 = (vx0 && vy0) ? 1.0f : 0.0f;
    o.m01 = (vx1 && vy0) ? 1.0f : 0.0f;
    o.m10 = (vx0 && vy1) ? 1.0f : 0.0f;
    o.m11 = (vx1 && vy1) ? 1.0f : 0.0f;
}

__device__ __forceinline__ float bl_sample(const float* __restrict__ plane, const BL& o) {
    float v00 = __fmul_rn(plane[o.i00], o.m00);
    float v01 = __fmul_rn(plane[o.i01], o.m01);
    float v10 = __fmul_rn(plane[o.i10], o.m10);
    float v11 = __fmul_rn(plane[o.i11], o.m11);
    float owx = __fsub_rn(1.0f, o.wx), owy = __fsub_rn(1.0f, o.wy);
    float t0 = __fmul_rn(__fmul_rn(v00, owx),  owy);
    float t1 = __fmul_rn(__fmul_rn(v01, o.wx), owy);
    float t2 = __fmul_rn(__fmul_rn(v10, owx),  o.wy);
    float t3 = __fmul_rn(__fmul_rn(v11, o.wx), o.wy);
    return __fadd_rn(__fadd_rn(__fadd_rn(t0, t1), t2), t3);
}

// ───────────────────────── k_prep ─────────────────────────
// One block per batch. top2 -> smem, keys -> smem, early-exit radix select
// (pass 1 scans all 7168 keys, later passes scan only the shrinking candidate
// bin), union(definite winners, candidates) <= 1024 -> bitonic sort -> points.
#define PR_ST2   0
#define PR_KEYS  32768
#define PR_CAND  90112
#define PR_BUF   147456
#define PR_HIST  155648
#define PR_SCAN  156672
#define PR_CTRL  157696
#define PR_SMEM  157728

__global__ void __launch_bounds__(1024) k_prep(const float* __restrict__ coarse,
                                               const float* __restrict__ over_gen,
                                               const float* __restrict__ coverage,
                                               float* __restrict__ pts_out) {
    extern __shared__ char smraw[];
    float*    st2  = (float*)(smraw + PR_ST2);
    ull*      keys = (ull*)(smraw + PR_KEYS);
    ull*      cand = (ull*)(smraw + PR_CAND);
    ull*      buf  = (ull*)(smraw + PR_BUF);
    unsigned* hist = (unsigned*)(smraw + PR_HIST);
    unsigned* scan = (unsigned*)(smraw + PR_SCAN);
    int*      s_sel  = (int*)(smraw + PR_CTRL);
    int*      s_rank = (int*)(smraw + PR_CTRL + 4);
    int*      s_wcnt = (int*)(smraw + PR_CTRL + 8);
    int*      s_ccnt = (int*)(smraw + PR_CTRL + 12);

    int b = blockIdx.x;
    int t = threadIdx.x;

    // top-2 over 7 channels, into smem
    const float* cb = coarse + (size_t)b * CCH * 4096;
    for (int pix = t; pix < 4096; pix += 1024) {
        float m1 = __int_as_float(0xff800000), m2 = m1;
#pragma unroll
        for (int c = 0; c < CCH; c++) {
            float v = cb[c * 4096 + pix];
            if (v > m1) { m2 = m1; m1 = v; }
            else if (v > m2) { m2 = v; }
        }
        st2[pix]        = m1;
        st2[4096 + pix] = m2;
    }
    if (t == 0) { *s_wcnt = 0; }
    __syncthreads();

    // uncertainty + composite keys (value desc via order-mapped ~bits, idx asc)
    const float2* og = (const float2*)over_gen + (size_t)b * NOVER;
    for (int i = t; i < NOVER; i += 1024) {
        float2 p = og[i];
        BL o;
        bl_setup(p.x, p.y, CW, o);
        float s0 = bl_sample(st2, o);
        float s1 = bl_sample(st2 + 4096, o);
        float un = -__fsub_rn(s0, s1);
        unsigned u = __float_as_uint(un);
        u = (u & 0x80000000u) ? ~u : (u ^ 0x80000000u);
        keys[i] = ((ull)(~u) << 13) | (unsigned)i;
    }
    __syncthreads();

    // early-exit radix select
    ull* src = keys;
    ull* dstc = cand;
    int m = NOVER;
    int rank = NIMP;
    int total = 0;
    for (int byte = 5; byte >= 0; byte--) {
        int sh = byte * 8;
        if (t < 256) hist[t] = 0;
        __syncthreads();
        for (int i = t; i < m; i += 1024)
            atomicAdd(&hist[(unsigned)(src[i] >> sh) & 255u], 1u);
        __syncthreads();
        if (t < 256) scan[t] = hist[t];
        __syncthreads();
        for (int off = 1; off < 256; off <<= 1) {
            unsigned v = 0;
            if (t < 256) { v = scan[t]; if (t >= off) v += scan[t - off]; }
            __syncthreads();
            if (t < 256) scan[t] = v;
            __syncthreads();
        }
        if (t < 256) {
            unsigned incl = scan[t], excl = incl - hist[t];
            if (excl < (unsigned)rank && (unsigned)rank <= incl) {
                *s_sel  = t;
                *s_rank = rank - (int)excl;
            }
        }
        if (t == 0) *s_ccnt = 0;
        __syncthreads();
        int sel = *s_sel;
        rank = *s_rank;
        // partition: digit<sel -> definite winner; ==sel -> candidate
        for (int i = t; i < m; i += 1024) {
            ull k = src[i];
            int d = (int)((unsigned)(k >> sh) & 255u);
            if (d < sel)       buf[atomicAdd(s_wcnt, 1)] = k;
            else if (d == sel) dstc[atomicAdd(s_ccnt, 1)] = k;
        }
        __syncthreads();
        m = *s_ccnt;
        int w = *s_wcnt;
        if (w + m <= 1024) {
            for (int i = t; i < m; i += 1024) buf[w + i] = dstc[i];
            total = w + m;
            break;
        }
        ull* tmp = src; src = dstc; dstc = tmp;
        __syncthreads();
    }
    __syncthreads();
    // pad to 1024 and bitonic sort; first 768 = stable top-k
    if (t >= total) buf[t] = ~0ull;
    __syncthreads();
    for (unsigned k = 2; k <= 1024; k <<= 1) {
        for (unsigned j = k >> 1; j > 0; j >>= 1) {
            unsigned i = t, ixj = i ^ j;
            if (ixj > i) {
                ull a = buf[i], c = buf[ixj];
                bool up = ((i & k) == 0);
                if ((a > c) == up) { buf[i] = c; buf[ixj] = a; }
            }
            __syncthreads();
        }
    }

    float* dst = pts_out + (size_t)b * NPTS * 2;
    if (t < NIMP) {
        int n = (int)(buf[t] & 0x1FFFull);
        float2 p = og[n];
        dst[t * 2 + 0] = p.x;
        dst[t * 2 + 1] = p.y;
    } else {
        int i = t - NIMP;
        float2 p = ((const float2*)coverage)[(size_t)b * NCOV + i];
        dst[(NIMP + i) * 2 + 0] = p.x;
        dst[(NIMP + i) * 2 + 1] = p.y;
    }
}

// ───────────────────────── k_fused ─────────────────────────
// 512 CTAs x 32 points, 256 threads. Thread tile 4pt x 8col (cg=t&31, pg=t>>5).
// w1s plane-split layout: per kk row, even float4-chunks at [0..127], odd at
// [128..255] -> both warp LDS.128 reads are contiguous 512B = conflict-free.
// Pipelined: gather chunk c+1 (LDG->regs) + cp.async w1 chunk c overlap the
// packed-f32x2 GEMM on chunk c. Epilogue: relu + w2 partials + reduce.
// smem floats: sfb 2*27*36 | w1s 27*268 (reused as part 7168) | w2s 1792 | BL 640
#define FU_SFB   0
#define FU_W1S   1944
#define FU_W2S   9180
#define FU_CBL   10972
#define FU_TOT   11612   // floats -> 46448 bytes

#define CHK  27
#define SFS  36          // sfb row stride (16B-aligned rows)
#define W1R  268         // w1s row stride (1072B, 16B-aligned)

__global__ void __launch_bounds__(256, 2) k_fused(
    const float* __restrict__ fine, const float* __restrict__ coarse,
    const float* __restrict__ w1, const float* __restrict__ b1,
    const float* __restrict__ w2, const float* __restrict__ b2,
    const float* __restrict__ pts, float* __restrict__ rend)
{
    extern __shared__ float sm[];
    float* sfb = sm + FU_SFB;       // [2][27*36]
    float* w1s = sm + FU_W1S;       // [27][268] plane-split
    float* w2s = sm + FU_W2S;       // [256][7]
    float* cbl = sm + FU_CBL;
    int*   fi  = (int*)cbl;         // [4][32] fine idx
    float* fm  = cbl + 128;         // [4][32] fine mask
    float* fwx = cbl + 256;         // [32]
    float* fwy = cbl + 288;
    int*   ci  = (int*)(cbl + 320); // [4][32] coarse idx
    float* cm  = cbl + 448;
    float* cwx = cbl + 576;
    float* cwy = cbl + 608;
    float* part = w1s;              // reused after GEMM1 (needs 32*32*7=7168 <= 7236)

    int t   = threadIdx.x;
    int bp0 = blockIdx.x * 32;
    int b   = bp0 >> 10;
    int cg  = t & 31;               // col group: cols cg*8 .. cg*8+7
    int pg  = t >> 5;               // point group: pts pg*4 .. pg*4+3

    // prologue: BLs for 32 points (fine by t<32, coarse by t in [32,64))
    if (t < 32) {
        float2 p = ((const float2*)pts)[bp0 + t];
        BL o;
        bl_setup(p.x, p.y, FW, o);
        fi[0*32+t] = o.i00; fi[1*32+t] = o.i01; fi[2*32+t] = o.i10; fi[3*32+t] = o.i11;
        fm[0*32+t] = o.m00; fm[1*32+t] = o.m01; fm[2*32+t] = o.m10; fm[3*32+t] = o.m11;
        fwx[t] = o.wx; fwy[t] = o.wy;
    } else if (t < 64) {
        int p_ = t - 32;
        float2 p = ((const float2*)pts)[bp0 + p_];
        BL o;
        bl_setup(p.x, p.y, CW, o);
        ci[0*32+p_] = o.i00; ci[1*32+p_] = o.i01; ci[2*32+p_] = o.i10; ci[3*32+p_] = o.i11;
        cm[0*32+p_] = o.m00; cm[1*32+p_] = o.m01; cm[2*32+p_] = o.m10; cm[3*32+p_] = o.m11;
        cwx[p_] = o.wx; cwy[p_] = o.wy;
    }
    for (int i = t; i < HID * 7; i += 256) w2s[i] = w2[i];

    // accumulators: 4 pts x 8 cols as 4x4 packed f32x2, init with bias
    ull acc2[4][4];
#pragma unroll
    for (int j = 0; j < 4; j++) {
        ull bv = pack2(b1[cg * 8 + 2 * j], b1[cg * 8 + 2 * j + 1]);
        acc2[0][j] = bv; acc2[1][j] = bv; acc2[2][j] = bv; acc2[3][j] = bv;
    }
    __syncthreads();

    float gv[4][4];

    // gather chunk 0 (fine channels 0..26)
    {
#pragma unroll
        for (int s = 0; s < 4; s++) {
            int task = s * 256 + t;
            if (task < 32 * CHK) {
                int kk = task >> 5, p = task & 31;
                const float* pl = fine + ((size_t)b * FCH + kk) * 65536;
                gv[s][0] = pl[fi[0*32+p]]; gv[s][1] = pl[fi[1*32+p]];
                gv[s][2] = pl[fi[2*32+p]]; gv[s][3] = pl[fi[3*32+p]];
            }
        }
#pragma unroll
        for (int s = 0; s < 4; s++) {
            int task = s * 256 + t;
            if (task < 32 * CHK) {
                int kk = task >> 5, p = task & 31;
                float wx = fwx[p], wy = fwy[p];
                float owx = 1.0f - wx, owy = 1.0f - wy;
                float v = gv[s][0] * fm[0*32+p] * (owx*owy) + gv[s][1] * fm[1*32+p] * (wx*owy)
                        + gv[s][2] * fm[2*32+p] * (owx*wy)  + gv[s][3] * fm[3*32+p] * (wx*wy);
                sfb[kk * SFS + p] = v;
            }
        }
    }

    for (int c = 0; c < 5; c++) {
        __syncthreads();   // sfb[c&1] visible; prior compute done -> w1s free
        int k0 = c * CHK;
        // cp.async w1 chunk c: float4-chunk q of row kk -> plane (q&1), slot q>>1
        for (int i = t; i < CHK * 64; i += 256) {
            int kk = i >> 6, q = i & 63;
            int row = k0 + kk;
            int srow = (row < FCH) ? (CCH + row) : (row - FCH);
            cp_async16(&w1s[kk * W1R + (q & 1) * 128 + (q >> 1) * 4],
                       w1 + (size_t)srow * HID + q * 4);
        }
        CP_COMMIT();
        // issue gather LDGs for chunk c+1
        if (c < 4) {
            int k1 = (c + 1) * CHK;
#pragma unroll
            for (int s = 0; s < 4; s++) {
                int task = s * 256 + t;
                if (task < 32 * CHK) {
                    int kk = task >> 5, p = task & 31;
                    int ch = k1 + kk;
                    if (ch < FCH) {
                        const float* pl = fine + ((size_t)b * FCH + ch) * 65536;
                        gv[s][0] = pl[fi[0*32+p]]; gv[s][1] = pl[fi[1*32+p]];
                        gv[s][2] = pl[fi[2*32+p]]; gv[s][3] = pl[fi[3*32+p]];
                    } else {
                        const float* pl = coarse + ((size_t)b * CCH + (ch - FCH)) * 4096;
                        gv[s][0] = pl[ci[0*32+p]]; gv[s][1] = pl[ci[1*32+p]];
                        gv[s][2] = pl[ci[2*32+p]]; gv[s][3] = pl[ci[3*32+p]];
                    }
                }
            }
        }
        CP_WAIT0();
        __syncthreads();   // w1s chunk c ready for all threads

        // compute chunk c: 4pt x 8col packed f32x2
        const float* sb = sfb + (c & 1) * (CHK * SFS);
#pragma unroll 3
        for (int kk = 0; kk < CHK; kk++) {
            float4 fv = *(const float4*)&sb[kk * SFS + pg * 4];   // broadcast
            ull ff0 = pack2(fv.x, fv.x);
            ull ff1 = pack2(fv.y, fv.y);
            ull ff2 = pack2(fv.z, fv.z);
            ull ff3 = pack2(fv.w, fv.w);
            const float* wr = &w1s[kk * W1R];
            ulonglong2 wa = *(const ulonglong2*)(wr + cg * 4);        // cols 8cg..+3
            ulonglong2 wb = *(const ulonglong2*)(wr + 128 + cg * 4);  // cols 8cg+4..+7
            acc2[0][0] = fma2(wa.x, ff0, acc2[0][0]);
            acc2[0][1] = fma2(wa.y, ff0, acc2[0][1]);
            acc2[0][2] = fma2(wb.x, ff0, acc2[0][2]);
            acc2[0][3] = fma2(wb.y, ff0, acc2[0][3]);
            acc2[1][0] = fma2(wa.x, ff1, acc2[1][0]);
            acc2[1][1] = fma2(wa.y, ff1, acc2[1][1]);
            acc2[1][2] = fma2(wb.x, ff1, acc2[1][2]);
            acc2[1][3] = fma2(wb.y, ff1, acc2[1][3]);
            acc2[2][0] = fma2(wa.x, ff2, acc2[2][0]);
            acc2[2][1] = fma2(wa.y, ff2, acc2[2][1]);
            acc2[2][2] = fma2(wb.x, ff2, acc2[2][2]);
            acc2[2][3] = fma2(wb.y, ff2, acc2[2][3]);
            acc2[3][0] = fma2(wa.x, ff3, acc2[3][0]);
            acc2[3][1] = fma2(wa.y, ff3, acc2[3][1]);
            acc2[3][2] = fma2(wb.x, ff3, acc2[3][2]);
            acc2[3][3] = fma2(wb.y, ff3, acc2[3][3]);
        }

        // combine + store gathered chunk c+1 into other buffer
        if (c < 4) {
            int k1 = (c + 1) * CHK;
            float* so = sfb + ((c + 1) & 1) * (CHK * SFS);
#pragma unroll
            for (int s = 0; s < 4; s++) {
                int task = s * 256 + t;
                if (task < 32 * CHK) {
                    int kk = task >> 5, p = task & 31;
                    int ch = k1 + kk;
                    float wx, wy, m0, m1, m2, m3;
                    if (ch < FCH) {
                        wx = fwx[p]; wy = fwy[p];
                        m0 = fm[0*32+p]; m1 = fm[1*32+p]; m2 = fm[2*32+p]; m3 = fm[3*32+p];
                    } else {
                        wx = cwx[p]; wy = cwy[p];
                        m0 = cm[0*32+p]; m1 = cm[1*32+p]; m2 = cm[2*32+p]; m3 = cm[3*32+p];
                    }
                    float owx = 1.0f - wx, owy = 1.0f - wy;
                    float v = gv[s][0] * m0 * (owx*owy) + gv[s][1] * m1 * (wx*owy)
                            + gv[s][2] * m2 * (owx*wy)  + gv[s][3] * m3 * (wx*wy);
                    so[kk * SFS + p] = v;
                }
            }
        }
    }
    __syncthreads();   // all compute done; w1s free -> reuse as part

    // GEMM2 partials: relu(acc) * w2 over this thread's 8 d's, for 4 points
#pragma unroll
    for (int i = 0; i < 4; i++) {
        float pr[7];
#pragma unroll
        for (int k = 0; k < 7; k++) pr[k] = 0.0f;
#pragma unroll
        for (int j = 0; j < 4; j++) {
            float h0, h1;
            unpack2(acc2[i][j], h0, h1);
            h0 = fmaxf(h0, 0.0f); h1 = fmaxf(h1, 0.0f);
            const float* wr0 = &w2s[(cg * 8 + 2 * j) * 7];
            const float* wr1 = wr0 + 7;
#pragma unroll
            for (int k = 0; k < 7; k++) pr[k] += h0 * wr0[k] + h1 * wr1[k];
        }
        float* pp = &part[((pg * 4 + i) * 32 + cg) * 7];
#pragma unroll
        for (int k = 0; k < 7; k++) pp[k] = pr[k];
    }
    __syncthreads();

    // reduce across 32 col groups, add b2, write rend[b][k][p]
    for (int task = t; task < 32 * 7; task += 256) {
        int p = task / 7, k = task % 7;
        float s = b2[k];
#pragma unroll
        for (int c = 0; c < 32; c++) s += part[(p * 32 + c) * 7 + k];
        rend[((size_t)b * CCH + k) * NPTS + (bp0 & 1023) + p] = s;
    }
}

extern "C" void kernel_launch(void* const* d_in, const int* in_sizes, int n_in,
                              void* d_out, int out_size) {
    (void)in_sizes; (void)n_in; (void)out_size;
    const float* fine     = (const float*)d_in[0];
    const float* coarse   = (const float*)d_in[1];
    const float* w1       = (const float*)d_in[2];
    const float* b1       = (const float*)d_in[3];
    const float* w2       = (const float*)d_in[4];
    const float* b2       = (const float*)d_in[5];
    const float* over_gen = (const float*)d_in[6];
    const float* coverage = (const float*)d_in[7];

    float* rend = (float*)d_out;                 // [16][7][1024]
    float* pts  = rend + NB * CCH * NPTS;        // [16][1024][2]

    cudaFuncSetAttribute(k_prep,  cudaFuncAttributeMaxDynamicSharedMemorySize, PR_SMEM);
    cudaFuncSetAttribute(k_fused, cudaFuncAttributeMaxDynamicSharedMemorySize, FU_TOT * 4);

    k_prep<<<NB, 1024, PR_SMEM>>>(coarse, over_gen, coverage, pts);
    k_fused<<<NB * 32, 256, FU_TOT * 4>>>(fine, coarse, w1, b1, w2, b2, pts, rend);
}

// round 10
// speedup vs baseline: 2.4228x; 1.0465x over previous
#include <cuda_runtime.h>
#include <stdint.h>

#define NB    16
#define CCH   7
#define FCH   128
#define CW    64
#define FW    256
#define NPTS  1024
#define NIMP  768
#define NCOV  256
#define NOVER 7168
#define HID   256
#define FEATC 135

typedef unsigned long long ull;

// ───────────────────────── helpers ─────────────────────────

__device__ __forceinline__ ull fma2(ull a, ull b, ull c) {
    ull d;
    asm("fma.rn.f32x2 %0, %1, %2, %3;" : "=l"(d) : "l"(a), "l"(b), "l"(c));
    return d;
}
__device__ __forceinline__ ull pack2(float lo, float hi) {
    ull d;
    asm("mov.b64 %0, {%1, %2};" : "=l"(d) : "f"(lo), "f"(hi));
    return d;
}
__device__ __forceinline__ void unpack2(ull v, float& lo, float& hi) {
    asm("mov.b64 {%0, %1}, %2;" : "=f"(lo), "=f"(hi) : "l"(v));
}
__device__ __forceinline__ void cp_async16(void* dst, const void* src) {
    unsigned d = (unsigned)__cvta_generic_to_shared(dst);
    asm volatile("cp.async.ca.shared.global [%0], [%1], 16;\n" :: "r"(d), "l"(src));
}
#define CP_COMMIT() asm volatile("cp.async.commit_group;\n" ::: "memory")
#define CP_WAIT0()  asm volatile("cp.async.wait_group 0;\n" ::: "memory")

struct BL {
    int   i00, i01, i10, i11;
    float m00, m01, m10, m11;
    float wx, wy;
};

// Replicates the reference's point_sample coordinate math with explicit
// rounding (no FMA contraction) so the top-k selection is bit-stable.
__device__ __forceinline__ void bl_setup(float px, float py, int W, BL& o) {
    float gx = __fsub_rn(__fmul_rn(2.0f, px), 1.0f);
    float gy = __fsub_rn(__fmul_rn(2.0f, py), 1.0f);
    float x  = __fmul_rn(__fsub_rn(__fmul_rn(__fadd_rn(gx, 1.0f), (float)W), 1.0f), 0.5f);
    float y  = __fmul_rn(__fsub_rn(__fmul_rn(__fadd_rn(gy, 1.0f), (float)W), 1.0f), 0.5f);
    float x0f = floorf(x), y0f = floorf(y);
    o.wx = __fsub_rn(x, x0f);
    o.wy = __fsub_rn(y, y0f);
    float x1f = __fadd_rn(x0f, 1.0f), y1f = __fadd_rn(y0f, 1.0f);
    float wm1 = (float)(W - 1);
    bool vx0 = (x0f >= 0.0f) && (x0f <= wm1);
    bool vx1 = (x1f >= 0.0f) && (x1f <= wm1);
    bool vy0 = (y0f >= 0.0f) && (y0f <= wm1);
    bool vy1 = (y1f >= 0.0f) && (y1f <= wm1);
    int ix0 = min(max((int)x0f, 0), W - 1);
    int ix1 = min(max((int)x1f, 0), W - 1);
    int iy0 = min(max((int)y0f, 0), W - 1);
    int iy1 = min(max((int)y1f, 0), W - 1);
    o.i00 = iy0 * W + ix0; o.i01 = iy0 * W + ix1;
    o.i10 = iy1 * W + ix0; o.i11 = iy1 * W + ix1;
    o.m00 = (vx0 && vy0) ? 1.0f : 0.0f;
    o.m01 = (vx1 && vy0) ? 1.0f : 0.0f;
    o.m10 = (vx0 && vy1) ? 1.0f : 0.0f;
    o.m11 = (vx1 && vy1) ? 1.0f : 0.0f;
}

__device__ __forceinline__ float bl_sample(const float* __restrict__ plane, const BL& o) {
    float v00 = __fmul_rn(plane[o.i00], o.m00);
    float v01 = __fmul_rn(plane[o.i01], o.m01);
    float v10 = __fmul_rn(plane[o.i10], o.m10);
    float v11 = __fmul_rn(plane[o.i11], o.m11);
    float owx = __fsub_rn(1.0f, o.wx), owy = __fsub_rn(1.0f, o.wy);
    float t0 = __fmul_rn(__fmul_rn(v00, owx),  owy);
    float t1 = __fmul_rn(__fmul_rn(v01, o.wx), owy);
    float t2 = __fmul_rn(__fmul_rn(v10, owx),  o.wy);
    float t3 = __fmul_rn(__fmul_rn(v11, o.wx), o.wy);
    return __fadd_rn(__fadd_rn(__fadd_rn(t0, t1), t2), t3);
}

// ───────────────────────── k_prep ─────────────────────────
// One block per batch. top2 -> smem, keys -> smem, early-exit radix select,
// hybrid smem/shfl bitonic sort of <=1024 survivors, emit points.
#define PR_ST2   0
#define PR_KEYS  32768
#define PR_CAND  90112
#define PR_BUF   147456
#define PR_HIST  155648
#define PR_SCAN  156672
#define PR_CTRL  156800
#define PR_SMEM  156832

__global__ void __launch_bounds__(1024) k_prep(const float* __restrict__ coarse,
                                               const float* __restrict__ over_gen,
                                               const float* __restrict__ coverage,
                                               float* __restrict__ pts_out) {
    extern __shared__ char smraw[];
    float*    st2  = (float*)(smraw + PR_ST2);
    ull*      keys = (ull*)(smraw + PR_KEYS);
    ull*      cand = (ull*)(smraw + PR_CAND);
    ull*      buf  = (ull*)(smraw + PR_BUF);
    unsigned* hist = (unsigned*)(smraw + PR_HIST);
    unsigned* wsum = (unsigned*)(smraw + PR_SCAN);   // 8 warp sums
    int*      s_sel  = (int*)(smraw + PR_CTRL);
    int*      s_rank = (int*)(smraw + PR_CTRL + 4);
    int*      s_wcnt = (int*)(smraw + PR_CTRL + 8);
    int*      s_ccnt = (int*)(smraw + PR_CTRL + 12);

    int b = blockIdx.x;
    int t = threadIdx.x;

    // top-2 over 7 channels, into smem
    const float* cb = coarse + (size_t)b * CCH * 4096;
    for (int pix = t; pix < 4096; pix += 1024) {
        float m1 = __int_as_float(0xff800000), m2 = m1;
#pragma unroll
        for (int c = 0; c < CCH; c++) {
            float v = cb[c * 4096 + pix];
            if (v > m1) { m2 = m1; m1 = v; }
            else if (v > m2) { m2 = v; }
        }
        st2[pix]        = m1;
        st2[4096 + pix] = m2;
    }
    if (t == 0) { *s_wcnt = 0; }
    __syncthreads();

    // uncertainty + composite keys (value desc via order-mapped ~bits, idx asc)
    const float2* og = (const float2*)over_gen + (size_t)b * NOVER;
    for (int i = t; i < NOVER; i += 1024) {
        float2 p = og[i];
        BL o;
        bl_setup(p.x, p.y, CW, o);
        float s0 = bl_sample(st2, o);
        float s1 = bl_sample(st2 + 4096, o);
        float un = -__fsub_rn(s0, s1);
        unsigned u = __float_as_uint(un);
        u = (u & 0x80000000u) ? ~u : (u ^ 0x80000000u);
        keys[i] = ((ull)(~u) << 13) | (unsigned)i;
    }
    __syncthreads();

    // early-exit radix select
    ull* src = keys;
    ull* dstc = cand;
    int m = NOVER;
    int rank = NIMP;
    int total = 0;
    for (int byte = 5; byte >= 0; byte--) {
        int sh = byte * 8;
        if (t < 256) hist[t] = 0;
        __syncthreads();
        for (int i = t; i < m; i += 1024)
            atomicAdd(&hist[(unsigned)(src[i] >> sh) & 255u], 1u);
        __syncthreads();
        // shfl inclusive scan of the 256-bin histogram (threads 0..255)
        unsigned hv = (t < 256) ? hist[t] : 0;
        unsigned sv = hv;
#pragma unroll
        for (int off = 1; off < 32; off <<= 1) {
            unsigned n = __shfl_up_sync(0xffffffffu, sv, off);
            if ((t & 31) >= off) sv += n;
        }
        if (t < 256 && (t & 31) == 31) wsum[t >> 5] = sv;
        __syncthreads();
        if (t == 0) {
            unsigned run = 0;
#pragma unroll
            for (int w8 = 0; w8 < 8; w8++) { unsigned x = wsum[w8]; wsum[w8] = run; run += x; }
            *s_ccnt = 0;
        }
        __syncthreads();
        if (t < 256) {
            unsigned incl = sv + wsum[t >> 5];
            unsigned excl = incl - hv;
            if (excl < (unsigned)rank && (unsigned)rank <= incl) {
                *s_sel  = t;
                *s_rank = rank - (int)excl;
            }
        }
        __syncthreads();
        int sel = *s_sel;
        rank = *s_rank;
        // partition: digit<sel -> definite winner; ==sel -> candidate
        for (int i = t; i < m; i += 1024) {
            ull k = src[i];
            int d = (int)((unsigned)(k >> sh) & 255u);
            if (d < sel)       buf[atomicAdd(s_wcnt, 1)] = k;
            else if (d == sel) dstc[atomicAdd(s_ccnt, 1)] = k;
        }
        __syncthreads();
        m = *s_ccnt;
        int w = *s_wcnt;
        if (w + m <= 1024) {
            for (int i = t; i < m; i += 1024) buf[w + i] = dstc[i];
            total = w + m;
            break;
        }
        ull* tmp = src; src = dstc; dstc = tmp;
        __syncthreads();
    }
    __syncthreads();

    // hybrid bitonic sort: element in register, smem for j>=32, shfl for j<=16
    ull v = (t < total) ? buf[t] : ~0ull;
    for (unsigned k = 2; k <= 1024; k <<= 1) {
        unsigned j = k >> 1;
        for (; j >= 32; j >>= 1) {
            buf[t] = v;
            __syncthreads();
            ull c = buf[t ^ j];
            bool keepmin = (((t & k) == 0) == ((t & j) == 0));
            v = keepmin ? (v < c ? v : c) : (v < c ? c : v);
            __syncthreads();
        }
        for (; j > 0; j >>= 1) {
            ull c = __shfl_xor_sync(0xffffffffu, v, j);
            bool keepmin = (((t & k) == 0) == ((t & j) == 0));
            v = keepmin ? (v < c ? v : c) : (v < c ? c : v);
        }
    }

    float* dst = pts_out + (size_t)b * NPTS * 2;
    if (t < NIMP) {
        int n = (int)(v & 0x1FFFull);
        float2 p = og[n];
        dst[t * 2 + 0] = p.x;
        dst[t * 2 + 1] = p.y;
    } else {
        int i = t - NIMP;
        float2 p = ((const float2*)coverage)[(size_t)b * NCOV + i];
        dst[(NIMP + i) * 2 + 0] = p.x;
        dst[(NIMP + i) * 2 + 1] = p.y;
    }
}

// ───────────────────────── k_fused ─────────────────────────
// 1024 CTAs x 16 points, 256 threads. Thread tile 4pt x 4col
// (cg=t&63, pg=t>>6). Paired-x gather: per (row,pt,ch) one aligned float2
// covers x0,x1 when x0 even; odd lanes add one predicated float2.
// Pipeline per 27-ch chunk: cp.async w1 + gather LDGs overlap fma2 compute.
// smem floats: sfb 2*27*20=1080 | w1s/part 7168 | w2s 1792 | pt params 384
#define FU_SFB   0
#define FU_W1S   1080
#define FU_W2S   8248
#define FU_CBL   10040
#define FU_TOT   10424   // floats -> 41696 bytes

#define CHK   27
#define SFS   20        // sfb row stride
#define NTASK (CHK * 16)

__global__ void __launch_bounds__(256, 3) k_fused(
    const float* __restrict__ fine, const float* __restrict__ coarse,
    const float* __restrict__ w1, const float* __restrict__ b1,
    const float* __restrict__ w2, const float* __restrict__ b2,
    const float* __restrict__ pts, float* __restrict__ rend)
{
    extern __shared__ float sm[];
    float*  sfb  = sm + FU_SFB;        // [2][27*20]
    float*  w1s  = sm + FU_W1S;        // [27][256]; reused as part[16*64*7]
    float*  w2s  = sm + FU_W2S;        // [256][7]
    int4*   fidx = (int4*)(sm + FU_CBL);          // [16] halved f2 idx (eb0h, ib0h, eb1h, ib1h)
    float4* fpar = (float4*)(sm + FU_CBL + 64);   // [16] (wx, wy, xodd, sel1)
    float4* fmsk = (float4*)(sm + FU_CBL + 128);  // [16] (m00,m01,m10,m11)
    int4*   cidx = (int4*)(sm + FU_CBL + 192);
    float4* cpar = (float4*)(sm + FU_CBL + 256);
    float4* cmsk = (float4*)(sm + FU_CBL + 320);
    float*  part = w1s;

    int t   = threadIdx.x;
    int bp0 = blockIdx.x * 16;
    int b   = bp0 >> 10;
    int cg  = t & 63;               // col group: cols cg*4 .. cg*4+3
    int pg  = t >> 6;               // point group: pts pg*4 .. pg*4+3

    // prologue: per-point params (t<16 fine, 16<=t<32 coarse)
    if (t < 32) {
        int p_ = t & 15;
        int W  = (t < 16) ? FW : CW;
        float2 p = ((const float2*)pts)[bp0 + p_];
        BL o;
        bl_setup(p.x, p.y, W, o);
        int ix0 = o.i00 & (W - 1);
        int ix1 = o.i01 & (W - 1);
        int rb0 = o.i00 - ix0;
        int rb1 = o.i10 - ix0;
        int eb  = ix0 & ~1;
        int c2  = min(eb + 2, W - 2);
        int4  idx = make_int4((rb0 + eb) >> 1, (rb0 + c2) >> 1,
                              (rb1 + eb) >> 1, (rb1 + c2) >> 1);
        float4 par = make_float4(o.wx, o.wy, (float)(ix0 & 1),
                                 (ix1 == ix0 + 1) ? 1.0f : 0.0f);
        float4 msk = make_float4(o.m00, o.m01, o.m10, o.m11);
        if (t < 16) { fidx[p_] = idx; fpar[p_] = par; fmsk[p_] = msk; }
        else        { cidx[p_] = idx; cpar[p_] = par; cmsk[p_] = msk; }
    }
    for (int i = t; i < HID * 7; i += 256) w2s[i] = w2[i];

    // accumulators: 4 pts x 4 cols as 4x2 packed f32x2, init with bias
    ull acc2[4][2];
    {
        ull bv0 = pack2(b1[cg * 4 + 0], b1[cg * 4 + 1]);
        ull bv1 = pack2(b1[cg * 4 + 2], b1[cg * 4 + 3]);
#pragma unroll
        for (int i = 0; i < 4; i++) { acc2[i][0] = bv0; acc2[i][1] = bv1; }
    }
    __syncthreads();

    float2 a0[2], a1[2], b0[2], b1r[2];

    // gather chunk 0 (fine channels 0..26): issue then combine
#pragma unroll
    for (int s = 0; s < 2; s++) {
        int task = s * 256 + t;
        if (task < NTASK) {
            int kk = task >> 4, p = task & 15;
            const float2* pl2 = (const float2*)(fine + ((size_t)b * FCH + kk) * 65536);
            int4 ix = fidx[p];
            float4 par = fpar[p];
            a0[s] = pl2[ix.x]; a1[s] = pl2[ix.z];
            b0[s] = make_float2(0.f, 0.f); b1r[s] = b0[s];
            if (par.z != 0.0f) { b0[s] = pl2[ix.y]; b1r[s] = pl2[ix.w]; }
        }
    }
#pragma unroll
    for (int s = 0; s < 2; s++) {
        int task = s * 256 + t;
        if (task < NTASK) {
            int kk = task >> 4, p = task & 15;
            float4 par = fpar[p];
            float4 mk  = fmsk[p];
            bool xo = par.z != 0.0f, s1 = par.w != 0.0f;
            float vx00 = xo ? a0[s].y : a0[s].x;
            float t10  = xo ? b0[s].x : a0[s].y;
            float vx10 = s1 ? t10 : vx00;
            float vx01 = xo ? a1[s].y : a1[s].x;
            float t11  = xo ? b1r[s].x : a1[s].y;
            float vx11 = s1 ? t11 : vx01;
            float owx = 1.0f - par.x, owy = 1.0f - par.y;
            sfb[kk * SFS + p] = vx00 * mk.x * (owx * owy) + vx10 * mk.y * (par.x * owy)
                              + vx01 * mk.z * (owx * par.y) + vx11 * mk.w * (par.x * par.y);
        }
    }

    for (int c = 0; c < 5; c++) {
        __syncthreads();   // sfb[c&1] visible; prior compute done -> w1s free
        int k0 = c * CHK;
        // cp.async w1 chunk c (row kk -> w1s[kk*256 + ...])
        for (int i = t; i < CHK * 64; i += 256) {
            int kk = i >> 6, q = i & 63;
            int row = k0 + kk;
            int srow = (row < FCH) ? (CCH + row) : (row - FCH);
            cp_async16(&w1s[kk * 256 + q * 4], w1 + (size_t)srow * HID + q * 4);
        }
        CP_COMMIT();
        // issue paired-x gather LDGs for chunk c+1
        if (c < 4) {
            int k1 = (c + 1) * CHK;
#pragma unroll
            for (int s = 0; s < 2; s++) {
                int task = s * 256 + t;
                if (task < NTASK) {
                    int kk = task >> 4, p = task & 15;
                    int ch = k1 + kk;
                    const float2* pl2;
                    int4 ix; float4 par;
                    if (ch < FCH) {
                        pl2 = (const float2*)(fine + ((size_t)b * FCH + ch) * 65536);
                        ix = fidx[p]; par = fpar[p];
                    } else {
                        pl2 = (const float2*)(coarse + ((size_t)b * CCH + (ch - FCH)) * 4096);
                        ix = cidx[p]; par = cpar[p];
                    }
                    a0[s] = pl2[ix.x]; a1[s] = pl2[ix.z];
                    b0[s] = make_float2(0.f, 0.f); b1r[s] = b0[s];
                    if (par.z != 0.0f) { b0[s] = pl2[ix.y]; b1r[s] = pl2[ix.w]; }
                }
            }
        }
        CP_WAIT0();
        __syncthreads();   // w1s chunk c ready for all threads

        // compute chunk c: 4pt x 4col packed f32x2
        const float* sb = sfb + (c & 1) * (CHK * SFS);
#pragma unroll 3
        for (int kk = 0; kk < CHK; kk++) {
            float4 fv = *(const float4*)&sb[kk * SFS + pg * 4];      // broadcast
            ulonglong2 w = *(const ulonglong2*)&w1s[kk * 256 + cg * 4];
            ull f0 = pack2(fv.x, fv.x);
            ull f1 = pack2(fv.y, fv.y);
            ull f2v = pack2(fv.z, fv.z);
            ull f3 = pack2(fv.w, fv.w);
            acc2[0][0] = fma2(w.x, f0, acc2[0][0]);
            acc2[0][1] = fma2(w.y, f0, acc2[0][1]);
            acc2[1][0] = fma2(w.x, f1, acc2[1][0]);
            acc2[1][1] = fma2(w.y, f1, acc2[1][1]);
            acc2[2][0] = fma2(w.x, f2v, acc2[2][0]);
            acc2[2][1] = fma2(w.y, f2v, acc2[2][1]);
            acc2[3][0] = fma2(w.x, f3, acc2[3][0]);
            acc2[3][1] = fma2(w.y, f3, acc2[3][1]);
        }

        // combine + store gathered chunk c+1 into other buffer
        if (c < 4) {
            int k1 = (c + 1) * CHK;
            float* so = sfb + ((c + 1) & 1) * (CHK * SFS);
#pragma unroll
            for (int s = 0; s < 2; s++) {
                int task = s * 256 + t;
                if (task < NTASK) {
                    int kk = task >> 4, p = task & 15;
                    int ch = k1 + kk;
                    float4 par, mk;
                    if (ch < FCH) { par = fpar[p]; mk = fmsk[p]; }
                    else          { par = cpar[p]; mk = cmsk[p]; }
                    bool xo = par.z != 0.0f, s1 = par.w != 0.0f;
                    float vx00 = xo ? a0[s].y : a0[s].x;
                    float t10  = xo ? b0[s].x : a0[s].y;
                    float vx10 = s1 ? t10 : vx00;
                    float vx01 = xo ? a1[s].y : a1[s].x;
                    float t11  = xo ? b1r[s].x : a1[s].y;
                    float vx11 = s1 ? t11 : vx01;
                    float owx = 1.0f - par.x, owy = 1.0f - par.y;
                    so[kk * SFS + p] = vx00 * mk.x * (owx * owy) + vx10 * mk.y * (par.x * owy)
                                     + vx01 * mk.z * (owx * par.y) + vx11 * mk.w * (par.x * par.y);
                }
            }
        }
    }
    __syncthreads();   // all compute done; w1s free -> reuse as part

    // GEMM2 partials: relu(acc) * w2 over this thread's 4 d's, for 4 points
#pragma unroll
    for (int i = 0; i < 4; i++) {
        float h0, h1, h2, h3;
        unpack2(acc2[i][0], h0, h1);
        unpack2(acc2[i][1], h2, h3);
        h0 = fmaxf(h0, 0.0f); h1 = fmaxf(h1, 0.0f);
        h2 = fmaxf(h2, 0.0f); h3 = fmaxf(h3, 0.0f);
        const float* w20 = &w2s[(cg * 4 + 0) * 7];
        const float* w21 = w20 + 7;
        const float* w22 = w20 + 14;
        const float* w23 = w20 + 21;
        float* pp = &part[((pg * 4 + i) * 64 + cg) * 7];
#pragma unroll
        for (int k = 0; k < 7; k++)
            pp[k] = h0 * w20[k] + h1 * w21[k] + h2 * w22[k] + h3 * w23[k];
    }
    __syncthreads();

    // reduce across 64 col groups, add b2, write rend[b][k][p]
    if (t < 16 * 7) {
        int p = t / 7, k = t % 7;
        float s = b2[k];
#pragma unroll 8
        for (int c = 0; c < 64; c++) s += part[(p * 64 + c) * 7 + k];
        rend[((size_t)b * CCH + k) * NPTS + (bp0 & 1023) + p] = s;
    }
}

extern "C" void kernel_launch(void* const* d_in, const int* in_sizes, int n_in,
                              void* d_out, int out_size) {
    (void)in_sizes; (void)n_in; (void)out_size;
    const float* fine     = (const float*)d_in[0];
    const float* coarse   = (const float*)d_in[1];
    const float* w1       = (const float*)d_in[2];
    const float* b1       = (const float*)d_in[3];
    const float* w2       = (const float*)d_in[4];
    const float* b2       = (const float*)d_in[5];
    const float* over_gen = (const float*)d_in[6];
    const float* coverage = (const float*)d_in[7];

    float* rend = (float*)d_out;                 // [16][7][1024]
    float* pts  = rend + NB * CCH * NPTS;        // [16][1024][2]

    cudaFuncSetAttribute(k_prep,  cudaFuncAttributeMaxDynamicSharedMemorySize, PR_SMEM);
    cudaFuncSetAttribute(k_fused, cudaFuncAttributeMaxDynamicSharedMemorySize, FU_TOT * 4);

    k_prep<<<NB, 1024, PR_SMEM>>>(coarse, over_gen, coverage, pts);
    k_fused<<<NB * NPTS / 16, 256, FU_TOT * 4>>>(fine, coarse, w1, b1, w2, b2, pts, rend);
}